// round 7
// baseline (speedup 1.0000x reference)
#include <cuda_runtime.h>
#include <cuda_fp16.h>
#include <math.h>

#define NN   256
#define CIN  128
#define HH   4
#define DD   32
#define NPOS (NN*NN)
#define FULL 0xffffffffu

// ---------------- scratch (device globals) ----------------
__device__ __half g_Wh[CIN][512];          // [c][e] fp16: e<128 wq*scale, <256 wk, <384 wv, <512 wg
__device__ float  g_wbt[HH][CIN];          // tri-bias weights f32
__device__ __half g_Woh[CIN][CIN];         // [e][c] = w_o[c][e] fp16
__device__ __half g_q[NN][HH][NN][DD];
__device__ __half g_k[NN][HH][NN][DD];
__device__ __half g_v[NN][HH][NN][DD];
__device__ __half g_gate[(size_t)NPOS*CIN];
__device__ __half g_tbh[HH][NN][NN];       // [h][query][key] fp16
__device__ __half g_o[(size_t)NPOS*CIN];

// ---------------- helpers ----------------
__device__ __forceinline__ unsigned cvta_s(const void* p) {
    return (unsigned)__cvta_generic_to_shared(p);
}
__device__ __forceinline__ void ldsm4(uint4& d, unsigned a) {
    asm volatile("ldmatrix.sync.aligned.m8n8.x4.shared.b16 {%0,%1,%2,%3}, [%4];"
                 : "=r"(d.x), "=r"(d.y), "=r"(d.z), "=r"(d.w) : "r"(a));
}
__device__ __forceinline__ void ldsm4t(uint4& d, unsigned a) {
    asm volatile("ldmatrix.sync.aligned.m8n8.x4.trans.shared.b16 {%0,%1,%2,%3}, [%4];"
                 : "=r"(d.x), "=r"(d.y), "=r"(d.z), "=r"(d.w) : "r"(a));
}
__device__ __forceinline__ void mma16(float4& d, unsigned a0, unsigned a1, unsigned a2, unsigned a3,
                                      unsigned b0, unsigned b1) {
    asm volatile("mma.sync.aligned.m16n8k16.row.col.f32.f16.f16.f32 "
                 "{%0,%1,%2,%3},{%4,%5,%6,%7},{%8,%9},{%0,%1,%2,%3};"
                 : "+f"(d.x), "+f"(d.y), "+f"(d.z), "+f"(d.w)
                 : "r"(a0), "r"(a1), "r"(a2), "r"(a3), "r"(b0), "r"(b1));
}
__device__ __forceinline__ unsigned packh2(float lo, float hi) {
    unsigned r;
    asm("cvt.rn.f16x2.f32 %0, %1, %2;" : "=r"(r) : "f"(hi), "f"(lo));
    return r;
}

// ---------------- weight prep ----------------
__global__ void prep_kernel(const float* __restrict__ wb, const float* __restrict__ wq,
                            const float* __restrict__ wk, const float* __restrict__ wv,
                            const float* __restrict__ wg, const float* __restrict__ wo) {
    int idx = blockIdx.x * blockDim.x + threadIdx.x;
    if (idx < CIN * 512) {
        int c = idx >> 9, e = idx & 511;
        float val;
        if      (e < 128) val = wq[e * CIN + c] * 0.17677669529663687f;   // 1/sqrt(32)
        else if (e < 256) val = wk[(e - 128) * CIN + c];
        else if (e < 384) val = wv[(e - 256) * CIN + c];
        else              val = wg[(e - 384) * CIN + c];
        g_Wh[c][e] = __float2half(val);
    }
    if (idx < HH * CIN) {
        int h = idx >> 7, c = idx & 127;
        g_wbt[h][c] = wb[h * CIN + c];
    }
    if (idx < CIN * CIN) {
        int e = idx >> 7, c = idx & 127;
        g_Woh[e][c] = __float2half(wo[c * CIN + e]);
    }
}

// ---------------- fused LN + {q,k,v,gate} fp16-mma projection + tri-bias ----------------
// 128 threads, 64 rows/CTA, 1024 CTAs. A-fragments hoisted (invariant over nc).
struct LnSmem {
    __half xs[64][136];        // 64 rows x 128 (+8 pad, row 272B)
    __half Bs[128][72];        // single-buffered 64-col weight chunk (row 144B)
    float mu[64], rs[64];
};

__global__ __launch_bounds__(128, 4) void lnproj_kernel(const float* __restrict__ x,
                                                        const float* __restrict__ lnw,
                                                        const float* __restrict__ lnb,
                                                        const float* __restrict__ bg) {
    extern __shared__ char sraw[];
    LnSmem& S = *(LnSmem*)sraw;

    int t = threadIdx.x;
    int p0 = blockIdx.x * 64;
    int w = t >> 5, lane = t & 31;
    int gid = lane >> 2, tig = lane & 3;

    // LN stats: warp w handles rows w*16..w*16+15
    for (int rr = 0; rr < 16; rr++) {
        int r = w * 16 + rr;
        const float* xp = x + (size_t)(p0 + r) * CIN;
        float v0 = xp[lane], v1 = xp[lane + 32], v2 = xp[lane + 64], v3 = xp[lane + 96];
        float s = v0 + v1 + v2 + v3;
        float q = v0 * v0 + v1 * v1 + v2 * v2 + v3 * v3;
        #pragma unroll
        for (int off = 16; off; off >>= 1) {
            s += __shfl_down_sync(FULL, s, off);
            q += __shfl_down_sync(FULL, q, off);
        }
        if (lane == 0) {
            float m = s * (1.f / 128.f);
            S.mu[r] = m;
            S.rs[r] = rsqrtf(q * (1.f / 128.f) - m * m + 1e-5f);
        }
    }
    __syncthreads();

    // normalize -> fp16 xs
    for (int idx = t * 4; idx < 64 * 128; idx += 512) {
        int r = idx >> 7, c = idx & 127;
        float4 xv = *(const float4*)(x + (size_t)(p0 + r) * CIN + c);
        float4 wv = *(const float4*)(lnw + c);
        float4 bv = *(const float4*)(lnb + c);
        float m = S.mu[r], rs = S.rs[r];
        *(__half2*)&S.xs[r][c]     = __floats2half2_rn((xv.x - m) * rs * wv.x + bv.x,
                                                       (xv.y - m) * rs * wv.y + bv.y);
        *(__half2*)&S.xs[r][c + 2] = __floats2half2_rn((xv.z - m) * rs * wv.z + bv.z,
                                                       (xv.w - m) * rs * wv.w + bv.w);
    }
    __syncthreads();

    int wm = w >> 1, wn = w & 1;              // warp tile: 32 rows x 32 cols of 64-chunk
    int m8 = lane >> 3, r8 = lane & 7;

    // hoist A-fragments: 8 ksteps x 2 m-tiles (xs invariant over nc loop)
    unsigned aBase = cvta_s(&S.xs[wm * 32 + (m8 & 1) * 8 + r8][(m8 >> 1) * 8]);
    uint4 af0[8], af1[8];
    #pragma unroll
    for (int ks = 0; ks < 8; ks++) {
        ldsm4(af0[ks], aBase + ks * 32);
        ldsm4(af1[ks], aBase + ks * 32 + 4352);   // +16 rows (16*272B)
    }

    unsigned bBase = cvta_s(&S.Bs[(m8 & 1) * 8 + r8][wn * 32 + (m8 >> 1) * 8]);

    int p_lo0 = p0 + wm * 32 + gid;
    int ii = p_lo0 >> 8;

    for (int nc = 0; nc < 8; nc++) {
        __syncthreads();   // prior compute done reading Bs
        for (int f = t; f < 1024; f += 128) {
            int k = f >> 3, c8 = (f & 7) * 8;
            *(uint4*)&S.Bs[k][c8] = *(const uint4*)&g_Wh[k][nc * 64 + c8];
        }
        __syncthreads();

        float4 acc[2][4];
        #pragma unroll
        for (int mt = 0; mt < 2; mt++)
            #pragma unroll
            for (int nt = 0; nt < 4; nt++) acc[mt][nt] = make_float4(0.f, 0.f, 0.f, 0.f);

        #pragma unroll
        for (int ks = 0; ks < 8; ks++) {
            uint4 B0, B1;
            ldsm4t(B0, bBase + ks * 2304);            // +16 k-rows (16*144B)
            ldsm4t(B1, bBase + ks * 2304 + 32);       // +16 n-cols
            mma16(acc[0][0], af0[ks].x, af0[ks].y, af0[ks].z, af0[ks].w, B0.x, B0.y);
            mma16(acc[0][1], af0[ks].x, af0[ks].y, af0[ks].z, af0[ks].w, B0.z, B0.w);
            mma16(acc[0][2], af0[ks].x, af0[ks].y, af0[ks].z, af0[ks].w, B1.x, B1.y);
            mma16(acc[0][3], af0[ks].x, af0[ks].y, af0[ks].z, af0[ks].w, B1.z, B1.w);
            mma16(acc[1][0], af1[ks].x, af1[ks].y, af1[ks].z, af1[ks].w, B0.x, B0.y);
            mma16(acc[1][1], af1[ks].x, af1[ks].y, af1[ks].z, af1[ks].w, B0.z, B0.w);
            mma16(acc[1][2], af1[ks].x, af1[ks].y, af1[ks].z, af1[ks].w, B1.x, B1.y);
            mma16(acc[1][3], af1[ks].x, af1[ks].y, af1[ks].z, af1[ks].w, B1.z, B1.w);
        }

        // epilogue to gmem
        int sel = nc >> 1;   // 0=q 1=k 2=v 3=gate
        #pragma unroll
        for (int mt = 0; mt < 2; mt++) {
            int p_lo = p_lo0 + mt * 16;
            int jj_lo = p_lo & 255, jj_hi = jj_lo + 8;
            #pragma unroll
            for (int nt = 0; nt < 4; nt++) {
                int e0 = nc * 64 + wn * 32 + nt * 8 + 2 * tig;
                int loc = e0 & 127;
                int hh = loc >> 5, d0 = loc & 31;
                float4 a = acc[mt][nt];
                if (sel == 0) {
                    *(__half2*)&g_q[ii][hh][jj_lo][d0] = __floats2half2_rn(a.x, a.y);
                    *(__half2*)&g_q[ii][hh][jj_hi][d0] = __floats2half2_rn(a.z, a.w);
                } else if (sel == 1) {
                    *(__half2*)&g_k[ii][hh][jj_lo][d0] = __floats2half2_rn(a.x, a.y);
                    *(__half2*)&g_k[ii][hh][jj_hi][d0] = __floats2half2_rn(a.z, a.w);
                } else if (sel == 2) {
                    *(__half2*)&g_v[ii][hh][jj_lo][d0] = __floats2half2_rn(a.x, a.y);
                    *(__half2*)&g_v[ii][hh][jj_hi][d0] = __floats2half2_rn(a.z, a.w);
                } else {
                    float2 bg2 = *(const float2*)(bg + loc);
                    float glx = 1.f / (1.f + __expf(-(a.x + bg2.x)));
                    float gly = 1.f / (1.f + __expf(-(a.y + bg2.y)));
                    float ghx = 1.f / (1.f + __expf(-(a.z + bg2.x)));
                    float ghy = 1.f / (1.f + __expf(-(a.w + bg2.y)));
                    *(__half2*)(g_gate + (size_t)p_lo * CIN + loc) = __floats2half2_rn(glx, gly);
                    *(__half2*)(g_gate + ((size_t)p_lo + 8) * CIN + loc) = __floats2half2_rn(ghx, ghy);
                }
            }
        }
    }

    // triangle bias: 64 rows x 4 heads = 256 pairs
    for (int pp = t; pp < 256; pp += 128) {
        int rr = pp >> 2, hh = pp & 3;
        const float* wv = g_wbt[hh];
        float a = 0.f;
        #pragma unroll 16
        for (int c = 0; c < 128; c += 2) {
            float2 fx = __half22float2(*(__half2*)&S.xs[rr][c]);
            a += fx.x * wv[c] + fx.y * wv[c + 1];
        }
        int p = p0 + rr;
        g_tbh[hh][p >> 8][p & 255] = __float2half(a);
    }
}

// ---------------- fp16-mma flash attention + gating ----------------
// 128 threads, 64 queries/CTA, grid 4096 = 256 i x 4 h x 4 q-tiles
struct AttnSmem {
    __half Qs[64][40];
    __half Ks[256][40];
    __half Vs[256][40];
    float mbs[256];
};

__global__ __launch_bounds__(128, 4) void attn_kernel(const float* __restrict__ mask) {
    extern __shared__ char sraw[];
    AttnSmem& S = *(AttnSmem*)sraw;

    int bid = blockIdx.x;
    int i = bid >> 4;
    int h = (bid >> 2) & 3;
    int qt = bid & 3;
    int t = threadIdx.x;
    int w = t >> 5, lane = t & 31;
    int gid = lane >> 2, tig = lane & 3;

    const __half* qg = &g_q[i][h][qt * 64][0];
    for (int f = t; f < 256; f += 128) {
        int r = f >> 2, c8 = (f & 3) * 8;
        *(uint4*)&S.Qs[r][c8] = *(const uint4*)(qg + r * 32 + c8);
    }
    const __half* kg = &g_k[i][h][0][0];
    const __half* vg = &g_v[i][h][0][0];
    for (int f = t; f < 1024; f += 128) {
        int r = f >> 2, c8 = (f & 3) * 8;
        *(uint4*)&S.Ks[r][c8] = *(const uint4*)(kg + r * 32 + c8);
        *(uint4*)&S.Vs[r][c8] = *(const uint4*)(vg + r * 32 + c8);
    }
    S.mbs[t]       = 1e9f * (mask[i * NN + t] - 1.0f);
    S.mbs[t + 128] = 1e9f * (mask[i * NN + t + 128] - 1.0f);
    __syncthreads();

    int m8 = lane >> 3, r8 = lane & 7;

    // Q fragments (resident): rows w*16..w*16+15, d=32 -> 2 ksteps
    unsigned qA = cvta_s(&S.Qs[w * 16 + (m8 & 1) * 8 + r8][(m8 >> 1) * 8]);
    uint4 aq0, aq1;
    ldsm4(aq0, qA);
    ldsm4(aq1, qA + 32);

    unsigned kA = cvta_s(&S.Ks[(m8 & 1) * 8 + r8][(m8 >> 1) * 8]);
    unsigned vA = cvta_s(&S.Vs[(m8 & 1) * 8 + r8][(m8 >> 1) * 8]);

    float4 oacc[4];
    #pragma unroll
    for (int n = 0; n < 4; n++) oacc[n] = make_float4(0.f, 0.f, 0.f, 0.f);
    float l_lo = 0.f, l_hi = 0.f;

    int q_lo = qt * 64 + w * 16 + gid, q_hi = q_lo + 8;
    const __half* tb_lo = &g_tbh[h][q_lo][0];
    const __half* tb_hi = &g_tbh[h][q_hi][0];

    for (int kb = 0; kb < 4; kb++) {
        int kbase = kb * 64;

        // S = Q @ K^T   (K stored [key][d] is col-major kxn -> NON-trans ldsm)
        float4 s[8];
        #pragma unroll
        for (int nt = 0; nt < 8; nt++) s[nt] = make_float4(0.f, 0.f, 0.f, 0.f);
        #pragma unroll
        for (int ntp = 0; ntp < 4; ntp++) {
            unsigned ka = kA + (kbase + ntp * 16) * 80;
            uint4 B0, B1;
            ldsm4(B0, ka);
            ldsm4(B1, ka + 32);
            mma16(s[2 * ntp],     aq0.x, aq0.y, aq0.z, aq0.w, B0.x, B0.z);
            mma16(s[2 * ntp],     aq1.x, aq1.y, aq1.z, aq1.w, B1.x, B1.z);
            mma16(s[2 * ntp + 1], aq0.x, aq0.y, aq0.z, aq0.w, B0.y, B0.w);
            mma16(s[2 * ntp + 1], aq1.x, aq1.y, aq1.z, aq1.w, B1.y, B1.w);
        }

        // bias + exp + pack to fp16 A-fragments (register-only C->A)
        unsigned pa[4][4];
        #pragma unroll
        for (int nt = 0; nt < 8; nt++) {
            int c0 = kbase + nt * 8 + 2 * tig;
            float2 tl = __half22float2(*(const __half2*)(tb_lo + c0));
            float2 th = __half22float2(*(const __half2*)(tb_hi + c0));
            float mb0 = S.mbs[c0], mb1 = S.mbs[c0 + 1];
            float px = __expf(s[nt].x + tl.x + mb0);
            float py = __expf(s[nt].y + tl.y + mb1);
            float pz = __expf(s[nt].z + th.x + mb0);
            float pw = __expf(s[nt].w + th.y + mb1);
            l_lo += px + py;
            l_hi += pz + pw;
            int ktp = nt >> 1;
            if (!(nt & 1)) {
                pa[ktp][0] = packh2(px, py);
                pa[ktp][1] = packh2(pz, pw);
            } else {
                pa[ktp][2] = packh2(px, py);
                pa[ktp][3] = packh2(pz, pw);
            }
        }

        // O += P @ V   (V stored [key][d] = row-major kxn -> trans ldsm)
        #pragma unroll
        for (int ktp = 0; ktp < 4; ktp++) {
            unsigned va = vA + (kbase + ktp * 16) * 80;
            uint4 V0, V1;
            ldsm4t(V0, va);
            ldsm4t(V1, va + 32);
            mma16(oacc[0], pa[ktp][0], pa[ktp][1], pa[ktp][2], pa[ktp][3], V0.x, V0.y);
            mma16(oacc[1], pa[ktp][0], pa[ktp][1], pa[ktp][2], pa[ktp][3], V0.z, V0.w);
            mma16(oacc[2], pa[ktp][0], pa[ktp][1], pa[ktp][2], pa[ktp][3], V1.x, V1.y);
            mma16(oacc[3], pa[ktp][0], pa[ktp][1], pa[ktp][2], pa[ktp][3], V1.z, V1.w);
        }
    }

    l_lo += __shfl_xor_sync(FULL, l_lo, 1);
    l_lo += __shfl_xor_sync(FULL, l_lo, 2);
    l_hi += __shfl_xor_sync(FULL, l_hi, 1);
    l_hi += __shfl_xor_sync(FULL, l_hi, 2);
    float inv_lo = 1.f / l_lo, inv_hi = 1.f / l_hi;

    size_t base_lo = ((size_t)(i * NN + q_lo)) * CIN + h * DD;
    size_t base_hi = ((size_t)(i * NN + q_hi)) * CIN + h * DD;
    #pragma unroll
    for (int ntd = 0; ntd < 4; ntd++) {
        int d0 = ntd * 8 + 2 * tig;
        float2 gl = __half22float2(*(__half2*)(g_gate + base_lo + d0));
        float2 gh = __half22float2(*(__half2*)(g_gate + base_hi + d0));
        *(__half2*)(g_o + base_lo + d0) =
            __floats2half2_rn(oacc[ntd].x * inv_lo * gl.x, oacc[ntd].y * inv_lo * gl.y);
        *(__half2*)(g_o + base_hi + d0) =
            __floats2half2_rn(oacc[ntd].z * inv_hi * gh.x, oacc[ntd].w * inv_hi * gh.y);
    }
}

// ---------------- fp16-mma output projection ----------------
// 128 threads, 64 rows/CTA, grid 1024
struct OutSmem {
    __half os[64][136];     // 64 rows + 8 pad
    __half Ws[128][136];
};

__global__ __launch_bounds__(128, 4) void outproj_kernel(float* __restrict__ out,
                                                         const float* __restrict__ bo) {
    extern __shared__ char sraw[];
    OutSmem& S = *(OutSmem*)sraw;

    int t = threadIdx.x;
    int p0 = blockIdx.x * 64;
    int w = t >> 5, lane = t & 31;
    int gid = lane >> 2, tig = lane & 3;

    for (int f = t; f < 1024; f += 128) {
        int r = f >> 4, c8 = (f & 15) * 8;
        *(uint4*)&S.os[r][c8] = *(const uint4*)(g_o + (size_t)(p0 + r) * CIN + c8);
    }
    for (int f = t; f < 2048; f += 128) {
        int r = f >> 4, c8 = (f & 15) * 8;
        *(uint4*)&S.Ws[r][c8] = *(const uint4*)&g_Woh[r][c8];
    }
    __syncthreads();

    int wm = w >> 1, wn = w & 1;           // warp tile 32 rows x 64 cols
    int m8 = lane >> 3, r8 = lane & 7;

    unsigned aBase = cvta_s(&S.os[wm * 32 + (m8 & 1) * 8 + r8][(m8 >> 1) * 8]);
    unsigned bBase = cvta_s(&S.Ws[(m8 & 1) * 8 + r8][wn * 64 + (m8 >> 1) * 8]);

    float4 acc[2][8];
    #pragma unroll
    for (int mt = 0; mt < 2; mt++)
        #pragma unroll
        for (int nt = 0; nt < 8; nt++) acc[mt][nt] = make_float4(0.f, 0.f, 0.f, 0.f);

    #pragma unroll
    for (int ks = 0; ks < 8; ks++) {
        uint4 A0, A1;
        ldsm4(A0, aBase + ks * 32);
        ldsm4(A1, aBase + ks * 32 + 4352);   // +16 rows (16*272B)
        uint4 B[4];
        #pragma unroll
        for (int ngp = 0; ngp < 4; ngp++) ldsm4t(B[ngp], bBase + ks * 4352 + ngp * 32);
        #pragma unroll
        for (int ngp = 0; ngp < 4; ngp++) {
            mma16(acc[0][2 * ngp],     A0.x, A0.y, A0.z, A0.w, B[ngp].x, B[ngp].y);
            mma16(acc[0][2 * ngp + 1], A0.x, A0.y, A0.z, A0.w, B[ngp].z, B[ngp].w);
            mma16(acc[1][2 * ngp],     A1.x, A1.y, A1.z, A1.w, B[ngp].x, B[ngp].y);
            mma16(acc[1][2 * ngp + 1], A1.x, A1.y, A1.z, A1.w, B[ngp].z, B[ngp].w);
        }
    }

    #pragma unroll
    for (int mt = 0; mt < 2; mt++) {
        int p_lo = p0 + wm * 32 + mt * 16 + gid;
        int p_hi = p_lo + 8;
        #pragma unroll
        for (int nt = 0; nt < 8; nt++) {
            int c0 = wn * 64 + nt * 8 + 2 * tig;
            float2 bo2 = *(const float2*)(bo + c0);
            *(float2*)(out + (size_t)p_lo * CIN + c0) =
                make_float2(acc[mt][nt].x + bo2.x, acc[mt][nt].y + bo2.y);
            *(float2*)(out + (size_t)p_hi * CIN + c0) =
                make_float2(acc[mt][nt].z + bo2.x, acc[mt][nt].w + bo2.y);
        }
    }
}

extern "C" void kernel_launch(void* const* d_in, const int* in_sizes, int n_in,
                              void* d_out, int out_size) {
    (void)in_sizes; (void)n_in; (void)out_size;
    const float* x    = (const float*)d_in[0];
    const float* mask = (const float*)d_in[1];
    const float* lnw  = (const float*)d_in[2];
    const float* lnb  = (const float*)d_in[3];
    const float* wb   = (const float*)d_in[4];
    const float* wq   = (const float*)d_in[5];
    const float* wk   = (const float*)d_in[6];
    const float* wv   = (const float*)d_in[7];
    const float* wg   = (const float*)d_in[8];
    const float* wo   = (const float*)d_in[10];
    const float* bg   = (const float*)d_in[9];
    const float* bo   = (const float*)d_in[11];
    float* out = (float*)d_out;

    cudaFuncSetAttribute(lnproj_kernel,  cudaFuncAttributeMaxDynamicSharedMemorySize, (int)sizeof(LnSmem));
    cudaFuncSetAttribute(attn_kernel,    cudaFuncAttributeMaxDynamicSharedMemorySize, (int)sizeof(AttnSmem));
    cudaFuncSetAttribute(outproj_kernel, cudaFuncAttributeMaxDynamicSharedMemorySize, (int)sizeof(OutSmem));

    prep_kernel<<<256, 256>>>(wb, wq, wk, wv, wg, wo);
    lnproj_kernel<<<1024, 128, sizeof(LnSmem)>>>(x, lnw, lnb, bg);
    attn_kernel<<<4096, 128, sizeof(AttnSmem)>>>(mask);
    outproj_kernel<<<1024, 128, sizeof(OutSmem)>>>(out, bo);
}

// round 8
// speedup vs baseline: 1.0850x; 1.0850x over previous
#include <cuda_runtime.h>
#include <cuda_fp16.h>
#include <math.h>

#define NN   256
#define CIN  128
#define HH   4
#define DD   32
#define NPOS (NN*NN)
#define FULL 0xffffffffu

// ---------------- scratch (device globals) ----------------
__device__ __half g_Wh[CIN][512];          // [c][e] fp16: e<128 wq*scale, <256 wk, <384 wv, <512 wg
__device__ float  g_wbt[HH][CIN];          // tri-bias weights f32
__device__ __half g_Woh[CIN][CIN];         // [e][c] = w_o[c][e] fp16
__device__ __half g_q[NN][HH][NN][DD];
__device__ __half g_k[NN][HH][NN][DD];
__device__ __half g_v[NN][HH][NN][DD];
__device__ __half g_gate[(size_t)NPOS*CIN];
__device__ __half g_tbh[HH][NN][NN];       // [h][query][key] fp16
__device__ __half g_o[(size_t)NPOS*CIN];

// ---------------- helpers ----------------
__device__ __forceinline__ unsigned cvta_s(const void* p) {
    return (unsigned)__cvta_generic_to_shared(p);
}
__device__ __forceinline__ void ldsm4(uint4& d, unsigned a) {
    asm volatile("ldmatrix.sync.aligned.m8n8.x4.shared.b16 {%0,%1,%2,%3}, [%4];"
                 : "=r"(d.x), "=r"(d.y), "=r"(d.z), "=r"(d.w) : "r"(a));
}
__device__ __forceinline__ void ldsm4t(uint4& d, unsigned a) {
    asm volatile("ldmatrix.sync.aligned.m8n8.x4.trans.shared.b16 {%0,%1,%2,%3}, [%4];"
                 : "=r"(d.x), "=r"(d.y), "=r"(d.z), "=r"(d.w) : "r"(a));
}
__device__ __forceinline__ void mma16(float4& d, unsigned a0, unsigned a1, unsigned a2, unsigned a3,
                                      unsigned b0, unsigned b1) {
    asm volatile("mma.sync.aligned.m16n8k16.row.col.f32.f16.f16.f32 "
                 "{%0,%1,%2,%3},{%4,%5,%6,%7},{%8,%9},{%0,%1,%2,%3};"
                 : "+f"(d.x), "+f"(d.y), "+f"(d.z), "+f"(d.w)
                 : "r"(a0), "r"(a1), "r"(a2), "r"(a3), "r"(b0), "r"(b1));
}
__device__ __forceinline__ unsigned packh2(float lo, float hi) {
    unsigned r;
    asm("cvt.rn.f16x2.f32 %0, %1, %2;" : "=r"(r) : "f"(hi), "f"(lo));
    return r;
}

// ---------------- weight prep ----------------
__global__ void prep_kernel(const float* __restrict__ wb, const float* __restrict__ wq,
                            const float* __restrict__ wk, const float* __restrict__ wv,
                            const float* __restrict__ wg, const float* __restrict__ wo) {
    int idx = blockIdx.x * blockDim.x + threadIdx.x;
    if (idx < CIN * 512) {
        int c = idx >> 9, e = idx & 511;
        float val;
        if      (e < 128) val = wq[e * CIN + c] * 0.17677669529663687f;   // 1/sqrt(32)
        else if (e < 256) val = wk[(e - 128) * CIN + c];
        else if (e < 384) val = wv[(e - 256) * CIN + c];
        else              val = wg[(e - 384) * CIN + c];
        g_Wh[c][e] = __float2half(val);
    }
    if (idx < HH * CIN) {
        int h = idx >> 7, c = idx & 127;
        g_wbt[h][c] = wb[h * CIN + c];
    }
    if (idx < CIN * CIN) {
        int e = idx >> 7, c = idx & 127;
        g_Woh[e][c] = __float2half(wo[c * CIN + e]);
    }
}

// ---------------- fused LN + {q,k,v,gate} fp16-mma projection + tri-bias ----------------
// (R6 shape: 256 threads, 128 rows/CTA, double-buffered weight chunks)
struct LnSmem {
    __half xs[128][136];       // 128 data cols + 8 pad (row 272B)
    __half Bs[2][128][72];     // double-buffered 64-col weight chunks (row 144B)
    float mu[128], rs[128];
};

__global__ __launch_bounds__(256) void lnproj_kernel(const float* __restrict__ x,
                                                     const float* __restrict__ lnw,
                                                     const float* __restrict__ lnb,
                                                     const float* __restrict__ bg) {
    extern __shared__ char sraw[];
    LnSmem& S = *(LnSmem*)sraw;

    int t = threadIdx.x;
    int p0 = blockIdx.x * 128;
    int w = t >> 5, lane = t & 31;
    int gid = lane >> 2, tig = lane & 3;

    // LN stats
    for (int rr = 0; rr < 16; rr++) {
        int r = w * 16 + rr;
        const float* xp = x + (size_t)(p0 + r) * CIN;
        float v0 = xp[lane], v1 = xp[lane + 32], v2 = xp[lane + 64], v3 = xp[lane + 96];
        float s = v0 + v1 + v2 + v3;
        float q = v0 * v0 + v1 * v1 + v2 * v2 + v3 * v3;
        #pragma unroll
        for (int off = 16; off; off >>= 1) {
            s += __shfl_down_sync(FULL, s, off);
            q += __shfl_down_sync(FULL, q, off);
        }
        if (lane == 0) {
            float m = s * (1.f / 128.f);
            S.mu[r] = m;
            S.rs[r] = rsqrtf(q * (1.f / 128.f) - m * m + 1e-5f);
        }
    }
    __syncthreads();

    // normalize -> fp16 xs
    for (int idx = t * 4; idx < 128 * 128; idx += 1024) {
        int r = idx >> 7, c = idx & 127;
        float4 xv = *(const float4*)(x + (size_t)(p0 + r) * CIN + c);
        float4 wv = *(const float4*)(lnw + c);
        float4 bv = *(const float4*)(lnb + c);
        float m = S.mu[r], rs = S.rs[r];
        *(__half2*)&S.xs[r][c]     = __floats2half2_rn((xv.x - m) * rs * wv.x + bv.x,
                                                       (xv.y - m) * rs * wv.y + bv.y);
        *(__half2*)&S.xs[r][c + 2] = __floats2half2_rn((xv.z - m) * rs * wv.z + bv.z,
                                                       (xv.w - m) * rs * wv.w + bv.w);
    }
    // preload weight chunk 0
    for (int f = t; f < 1024; f += 256) {
        int k = f >> 3, c8 = (f & 7) * 8;
        *(uint4*)&S.Bs[0][k][c8] = *(const uint4*)&g_Wh[k][c8];
    }
    __syncthreads();

    int wm = w >> 1, wn = w & 1;              // warp tile: 32 rows x 32 cols of 64-chunk
    int m8 = lane >> 3, r8 = lane & 7;

    unsigned aBase = cvta_s(&S.xs[wm * 32 + (m8 & 1) * 8 + r8][(m8 >> 1) * 8]);
    unsigned bBase[2];
    bBase[0] = cvta_s(&S.Bs[0][(m8 & 1) * 8 + r8][wn * 32 + (m8 >> 1) * 8]);
    bBase[1] = cvta_s(&S.Bs[1][(m8 & 1) * 8 + r8][wn * 32 + (m8 >> 1) * 8]);

    int p_lo0 = p0 + wm * 32 + gid;
    int ii = p_lo0 >> 8;

    for (int nc = 0; nc < 8; nc++) {
        int cur = nc & 1;
        uint4 pre[4];
        if (nc < 7) {
            #pragma unroll
            for (int j = 0; j < 4; j++) {
                int f = t + j * 256;
                int k = f >> 3, c8 = (f & 7) * 8;
                pre[j] = *(const uint4*)&g_Wh[k][(nc + 1) * 64 + c8];
            }
        }

        float4 acc[2][4];
        #pragma unroll
        for (int mt = 0; mt < 2; mt++)
            #pragma unroll
            for (int nt = 0; nt < 4; nt++) acc[mt][nt] = make_float4(0.f, 0.f, 0.f, 0.f);

        unsigned bb = bBase[cur];
        #pragma unroll
        for (int ks = 0; ks < 8; ks++) {
            uint4 A0, A1, B0, B1;
            ldsm4(A0, aBase + ks * 32);
            ldsm4(A1, aBase + ks * 32 + 4352);     // +16 rows (16*272B)
            ldsm4t(B0, bb + ks * 2304);            // +16 k-rows (16*144B)
            ldsm4t(B1, bb + ks * 2304 + 32);       // +16 n-cols
            mma16(acc[0][0], A0.x, A0.y, A0.z, A0.w, B0.x, B0.y);
            mma16(acc[0][1], A0.x, A0.y, A0.z, A0.w, B0.z, B0.w);
            mma16(acc[0][2], A0.x, A0.y, A0.z, A0.w, B1.x, B1.y);
            mma16(acc[0][3], A0.x, A0.y, A0.z, A0.w, B1.z, B1.w);
            mma16(acc[1][0], A1.x, A1.y, A1.z, A1.w, B0.x, B0.y);
            mma16(acc[1][1], A1.x, A1.y, A1.z, A1.w, B0.z, B0.w);
            mma16(acc[1][2], A1.x, A1.y, A1.z, A1.w, B1.x, B1.y);
            mma16(acc[1][3], A1.x, A1.y, A1.z, A1.w, B1.z, B1.w);
        }

        // epilogue to gmem
        int sel = nc >> 1;   // 0=q 1=k 2=v 3=gate
        #pragma unroll
        for (int mt = 0; mt < 2; mt++) {
            int p_lo = p_lo0 + mt * 16;
            int jj_lo = p_lo & 255, jj_hi = jj_lo + 8;
            #pragma unroll
            for (int nt = 0; nt < 4; nt++) {
                int e0 = nc * 64 + wn * 32 + nt * 8 + 2 * tig;
                int loc = e0 & 127;
                int hh = loc >> 5, d0 = loc & 31;
                float4 a = acc[mt][nt];
                if (sel == 0) {
                    *(__half2*)&g_q[ii][hh][jj_lo][d0] = __floats2half2_rn(a.x, a.y);
                    *(__half2*)&g_q[ii][hh][jj_hi][d0] = __floats2half2_rn(a.z, a.w);
                } else if (sel == 1) {
                    *(__half2*)&g_k[ii][hh][jj_lo][d0] = __floats2half2_rn(a.x, a.y);
                    *(__half2*)&g_k[ii][hh][jj_hi][d0] = __floats2half2_rn(a.z, a.w);
                } else if (sel == 2) {
                    *(__half2*)&g_v[ii][hh][jj_lo][d0] = __floats2half2_rn(a.x, a.y);
                    *(__half2*)&g_v[ii][hh][jj_hi][d0] = __floats2half2_rn(a.z, a.w);
                } else {
                    float2 bg2 = *(const float2*)(bg + loc);
                    float glx = 1.f / (1.f + __expf(-(a.x + bg2.x)));
                    float gly = 1.f / (1.f + __expf(-(a.y + bg2.y)));
                    float ghx = 1.f / (1.f + __expf(-(a.z + bg2.x)));
                    float ghy = 1.f / (1.f + __expf(-(a.w + bg2.y)));
                    *(__half2*)(g_gate + (size_t)p_lo * CIN + loc) = __floats2half2_rn(glx, gly);
                    *(__half2*)(g_gate + ((size_t)p_lo + 8) * CIN + loc) = __floats2half2_rn(ghx, ghy);
                }
            }
        }

        __syncthreads();
        if (nc < 7) {
            #pragma unroll
            for (int j = 0; j < 4; j++) {
                int f = t + j * 256;
                int k = f >> 3, c8 = (f & 7) * 8;
                *(uint4*)&S.Bs[cur ^ 1][k][c8] = pre[j];
            }
        }
        __syncthreads();
    }

    // triangle bias (fp16 out)
    for (int pp = t; pp < 512; pp += 256) {
        int rr = pp >> 2, hh = pp & 3;
        const float* wv = g_wbt[hh];
        float a = 0.f;
        #pragma unroll 16
        for (int c = 0; c < 128; c += 2) {
            float2 fx = __half22float2(*(__half2*)&S.xs[rr][c]);
            a += fx.x * wv[c] + fx.y * wv[c + 1];
        }
        int p = p0 + rr;
        g_tbh[hh][p >> 8][p & 255] = __float2half(a);
    }
}

// ---------------- fp16-mma flash attention + gating ----------------
// CTA = (i, h): 256 threads, 8 warps, warp owns 32 queries. K/V staged ONCE.
struct AttnSmem {
    __half Qs[256][40];
    __half Ks[256][40];
    __half Vs[256][40];
    float mbs[256];
};

__global__ __launch_bounds__(256, 2) void attn_kernel(const float* __restrict__ mask) {
    extern __shared__ char sraw[];
    AttnSmem& S = *(AttnSmem*)sraw;

    int bid = blockIdx.x;
    int i = bid >> 2;
    int h = bid & 3;
    int t = threadIdx.x;
    int w = t >> 5, lane = t & 31;
    int gid = lane >> 2, tig = lane & 3;

    const __half* qg = &g_q[i][h][0][0];
    const __half* kg = &g_k[i][h][0][0];
    const __half* vg = &g_v[i][h][0][0];
    for (int f = t; f < 1024; f += 256) {
        int r = f >> 2, c8 = (f & 3) * 8;
        *(uint4*)&S.Qs[r][c8] = *(const uint4*)(qg + r * 32 + c8);
        *(uint4*)&S.Ks[r][c8] = *(const uint4*)(kg + r * 32 + c8);
        *(uint4*)&S.Vs[r][c8] = *(const uint4*)(vg + r * 32 + c8);
    }
    S.mbs[t] = 1e9f * (mask[i * NN + t] - 1.0f);
    __syncthreads();

    int m8 = lane >> 3, r8 = lane & 7;

    // Q fragments: warp rows w*32..w*32+31, 2 m-tiles x 2 ksteps
    unsigned qA = cvta_s(&S.Qs[w * 32 + (m8 & 1) * 8 + r8][(m8 >> 1) * 8]);
    uint4 aq[2][2];
    #pragma unroll
    for (int mt = 0; mt < 2; mt++) {
        ldsm4(aq[mt][0], qA + mt * 1280);        // +16 rows (16*80B)
        ldsm4(aq[mt][1], qA + mt * 1280 + 32);   // +16 cols (d16-31)
    }

    unsigned kA = cvta_s(&S.Ks[(m8 & 1) * 8 + r8][(m8 >> 1) * 8]);
    unsigned vA = cvta_s(&S.Vs[(m8 & 1) * 8 + r8][(m8 >> 1) * 8]);

    float4 oacc[2][4];
    #pragma unroll
    for (int mt = 0; mt < 2; mt++)
        #pragma unroll
        for (int n = 0; n < 4; n++) oacc[mt][n] = make_float4(0.f, 0.f, 0.f, 0.f);
    float l_lo[2] = {0.f, 0.f}, l_hi[2] = {0.f, 0.f};

    const __half* tb_base = &g_tbh[h][0][0];
    int q_row0 = w * 32 + gid;     // mt adds +16, hi adds +8

    for (int kb = 0; kb < 8; kb++) {
        int kbase = kb * 32;

        // S = Q @ K^T for 32 keys (K [key][d] col-major kxn -> NON-trans ldsm)
        float4 s[2][4];
        #pragma unroll
        for (int mt = 0; mt < 2; mt++)
            #pragma unroll
            for (int nt = 0; nt < 4; nt++) s[mt][nt] = make_float4(0.f, 0.f, 0.f, 0.f);

        #pragma unroll
        for (int ntp = 0; ntp < 2; ntp++) {
            unsigned ka = kA + (kbase + ntp * 16) * 80;
            uint4 B0, B1;
            ldsm4(B0, ka);
            ldsm4(B1, ka + 32);
            #pragma unroll
            for (int mt = 0; mt < 2; mt++) {
                mma16(s[mt][2 * ntp],     aq[mt][0].x, aq[mt][0].y, aq[mt][0].z, aq[mt][0].w, B0.x, B0.z);
                mma16(s[mt][2 * ntp],     aq[mt][1].x, aq[mt][1].y, aq[mt][1].z, aq[mt][1].w, B1.x, B1.z);
                mma16(s[mt][2 * ntp + 1], aq[mt][0].x, aq[mt][0].y, aq[mt][0].z, aq[mt][0].w, B0.y, B0.w);
                mma16(s[mt][2 * ntp + 1], aq[mt][1].x, aq[mt][1].y, aq[mt][1].z, aq[mt][1].w, B1.y, B1.w);
            }
        }

        // bias + exp + pack to fp16 A-fragments
        unsigned pa[2][2][4];
        #pragma unroll
        for (int mt = 0; mt < 2; mt++) {
            const __half* tb_lo = tb_base + (q_row0 + mt * 16) * NN;
            const __half* tb_hi = tb_lo + 8 * NN;
            #pragma unroll
            for (int nt = 0; nt < 4; nt++) {
                int c0 = kbase + nt * 8 + 2 * tig;
                float2 tl = __half22float2(*(const __half2*)(tb_lo + c0));
                float2 th = __half22float2(*(const __half2*)(tb_hi + c0));
                float mb0 = S.mbs[c0], mb1 = S.mbs[c0 + 1];
                float px = __expf(s[mt][nt].x + tl.x + mb0);
                float py = __expf(s[mt][nt].y + tl.y + mb1);
                float pz = __expf(s[mt][nt].z + th.x + mb0);
                float pw = __expf(s[mt][nt].w + th.y + mb1);
                l_lo[mt] += px + py;
                l_hi[mt] += pz + pw;
                int ktp = nt >> 1;
                if (!(nt & 1)) {
                    pa[mt][ktp][0] = packh2(px, py);
                    pa[mt][ktp][1] = packh2(pz, pw);
                } else {
                    pa[mt][ktp][2] = packh2(px, py);
                    pa[mt][ktp][3] = packh2(pz, pw);
                }
            }
        }

        // O += P @ V (V [key][d] row-major kxn -> trans ldsm)
        #pragma unroll
        for (int ktp = 0; ktp < 2; ktp++) {
            unsigned va = vA + (kbase + ktp * 16) * 80;
            uint4 V0, V1;
            ldsm4t(V0, va);
            ldsm4t(V1, va + 32);
            #pragma unroll
            for (int mt = 0; mt < 2; mt++) {
                mma16(oacc[mt][0], pa[mt][ktp][0], pa[mt][ktp][1], pa[mt][ktp][2], pa[mt][ktp][3], V0.x, V0.y);
                mma16(oacc[mt][1], pa[mt][ktp][0], pa[mt][ktp][1], pa[mt][ktp][2], pa[mt][ktp][3], V0.z, V0.w);
                mma16(oacc[mt][2], pa[mt][ktp][0], pa[mt][ktp][1], pa[mt][ktp][2], pa[mt][ktp][3], V1.x, V1.y);
                mma16(oacc[mt][3], pa[mt][ktp][0], pa[mt][ktp][1], pa[mt][ktp][2], pa[mt][ktp][3], V1.z, V1.w);
            }
        }
    }

    // finalize + gated store
    #pragma unroll
    for (int mt = 0; mt < 2; mt++) {
        float ll = l_lo[mt], lh = l_hi[mt];
        ll += __shfl_xor_sync(FULL, ll, 1);
        ll += __shfl_xor_sync(FULL, ll, 2);
        lh += __shfl_xor_sync(FULL, lh, 1);
        lh += __shfl_xor_sync(FULL, lh, 2);
        float inv_lo = 1.f / ll, inv_hi = 1.f / lh;

        int q_lo = q_row0 + mt * 16, q_hi = q_lo + 8;
        size_t base_lo = ((size_t)(i * NN + q_lo)) * CIN + h * DD;
        size_t base_hi = ((size_t)(i * NN + q_hi)) * CIN + h * DD;
        #pragma unroll
        for (int ntd = 0; ntd < 4; ntd++) {
            int d0 = ntd * 8 + 2 * tig;
            float2 gl = __half22float2(*(__half2*)(g_gate + base_lo + d0));
            float2 gh = __half22float2(*(__half2*)(g_gate + base_hi + d0));
            *(__half2*)(g_o + base_lo + d0) =
                __floats2half2_rn(oacc[mt][ntd].x * inv_lo * gl.x, oacc[mt][ntd].y * inv_lo * gl.y);
            *(__half2*)(g_o + base_hi + d0) =
                __floats2half2_rn(oacc[mt][ntd].z * inv_hi * gh.x, oacc[mt][ntd].w * inv_hi * gh.y);
        }
    }
}

// ---------------- fp16-mma output projection (R6 shape) ----------------
struct OutSmem {
    __half os[128][136];
    __half Ws[128][136];
};

__global__ __launch_bounds__(256) void outproj_kernel(float* __restrict__ out,
                                                      const float* __restrict__ bo) {
    extern __shared__ char sraw[];
    OutSmem& S = *(OutSmem*)sraw;

    int t = threadIdx.x;
    int p0 = blockIdx.x * 128;
    int w = t >> 5, lane = t & 31;
    int gid = lane >> 2, tig = lane & 3;

    for (int f = t; f < 2048; f += 256) {
        int r = f >> 4, c8 = (f & 15) * 8;
        *(uint4*)&S.os[r][c8] = *(const uint4*)(g_o + (size_t)(p0 + r) * CIN + c8);
        *(uint4*)&S.Ws[r][c8] = *(const uint4*)&g_Woh[r][c8];
    }
    __syncthreads();

    int wm = w >> 1, wn = w & 1;           // warp tile 32 rows x 64 cols
    int m8 = lane >> 3, r8 = lane & 7;

    unsigned aBase = cvta_s(&S.os[wm * 32 + (m8 & 1) * 8 + r8][(m8 >> 1) * 8]);
    unsigned bBase = cvta_s(&S.Ws[(m8 & 1) * 8 + r8][wn * 64 + (m8 >> 1) * 8]);

    float4 acc[2][8];
    #pragma unroll
    for (int mt = 0; mt < 2; mt++)
        #pragma unroll
        for (int nt = 0; nt < 8; nt++) acc[mt][nt] = make_float4(0.f, 0.f, 0.f, 0.f);

    #pragma unroll
    for (int ks = 0; ks < 8; ks++) {
        uint4 A0, A1;
        ldsm4(A0, aBase + ks * 32);
        ldsm4(A1, aBase + ks * 32 + 4352);   // +16 rows (16*272B)
        uint4 B[4];
        #pragma unroll
        for (int ngp = 0; ngp < 4; ngp++) ldsm4t(B[ngp], bBase + ks * 4352 + ngp * 32);
        #pragma unroll
        for (int ngp = 0; ngp < 4; ngp++) {
            mma16(acc[0][2 * ngp],     A0.x, A0.y, A0.z, A0.w, B[ngp].x, B[ngp].y);
            mma16(acc[0][2 * ngp + 1], A0.x, A0.y, A0.z, A0.w, B[ngp].z, B[ngp].w);
            mma16(acc[1][2 * ngp],     A1.x, A1.y, A1.z, A1.w, B[ngp].x, B[ngp].y);
            mma16(acc[1][2 * ngp + 1], A1.x, A1.y, A1.z, A1.w, B[ngp].z, B[ngp].w);
        }
    }

    #pragma unroll
    for (int mt = 0; mt < 2; mt++) {
        int p_lo = p0 + wm * 32 + mt * 16 + gid;
        int p_hi = p_lo + 8;
        #pragma unroll
        for (int nt = 0; nt < 8; nt++) {
            int c0 = wn * 64 + nt * 8 + 2 * tig;
            float2 bo2 = *(const float2*)(bo + c0);
            *(float2*)(out + (size_t)p_lo * CIN + c0) =
                make_float2(acc[mt][nt].x + bo2.x, acc[mt][nt].y + bo2.y);
            *(float2*)(out + (size_t)p_hi * CIN + c0) =
                make_float2(acc[mt][nt].z + bo2.x, acc[mt][nt].w + bo2.y);
        }
    }
}

extern "C" void kernel_launch(void* const* d_in, const int* in_sizes, int n_in,
                              void* d_out, int out_size) {
    (void)in_sizes; (void)n_in; (void)out_size;
    const float* x    = (const float*)d_in[0];
    const float* mask = (const float*)d_in[1];
    const float* lnw  = (const float*)d_in[2];
    const float* lnb  = (const float*)d_in[3];
    const float* wb   = (const float*)d_in[4];
    const float* wq   = (const float*)d_in[5];
    const float* wk   = (const float*)d_in[6];
    const float* wv   = (const float*)d_in[7];
    const float* wg   = (const float*)d_in[8];
    const float* bg   = (const float*)d_in[9];
    const float* wo   = (const float*)d_in[10];
    const float* bo   = (const float*)d_in[11];
    float* out = (float*)d_out;

    cudaFuncSetAttribute(lnproj_kernel,  cudaFuncAttributeMaxDynamicSharedMemorySize, (int)sizeof(LnSmem));
    cudaFuncSetAttribute(attn_kernel,    cudaFuncAttributeMaxDynamicSharedMemorySize, (int)sizeof(AttnSmem));
    cudaFuncSetAttribute(outproj_kernel, cudaFuncAttributeMaxDynamicSharedMemorySize, (int)sizeof(OutSmem));

    prep_kernel<<<256, 256>>>(wb, wq, wk, wv, wg, wo);
    lnproj_kernel<<<512, 256, sizeof(LnSmem)>>>(x, lnw, lnb, bg);
    attn_kernel<<<1024, 256, sizeof(AttnSmem)>>>(mask);
    outproj_kernel<<<512, 256, sizeof(OutSmem)>>>(out, bo);
}

// round 11
// speedup vs baseline: 1.1450x; 1.0553x over previous
#include <cuda_runtime.h>
#include <cuda_fp16.h>
#include <math.h>

#define NN   256
#define CIN  128
#define HH   4
#define DD   32
#define NPOS (NN*NN)
#define FULL 0xffffffffu

// ---------------- scratch (device globals) ----------------
__device__ __half g_Wh[CIN][512];          // [c][e] fp16: e<128 wq*scale, <256 wk, <384 wv, <512 wg
__device__ float  g_wbt[HH][CIN];          // tri-bias weights f32
__device__ __half g_Woh[CIN][CIN];         // [e][c] = w_o[c][e] fp16
__device__ __half g_q[NN][HH][NN][DD];
__device__ __half g_k[NN][HH][NN][DD];
__device__ __half g_v[NN][HH][NN][DD];
__device__ __half g_gate[(size_t)NPOS*CIN];
__device__ __half g_tbh[HH][NN][NN];       // [h][query][key] fp16
__device__ __half g_o[(size_t)NPOS*CIN];

// ---------------- helpers ----------------
__device__ __forceinline__ unsigned cvta_s(const void* p) {
    return (unsigned)__cvta_generic_to_shared(p);
}
__device__ __forceinline__ void cpa16(unsigned dst, const void* src) {
    asm volatile("cp.async.cg.shared.global [%0], [%1], 16;" :: "r"(dst), "l"(src) : "memory");
}
#define CPA_COMMIT() asm volatile("cp.async.commit_group;" ::: "memory")
#define CPA_WAIT0()  asm volatile("cp.async.wait_group 0;" ::: "memory")

__device__ __forceinline__ void ldsm4(uint4& d, unsigned a) {
    asm volatile("ldmatrix.sync.aligned.m8n8.x4.shared.b16 {%0,%1,%2,%3}, [%4];"
                 : "=r"(d.x), "=r"(d.y), "=r"(d.z), "=r"(d.w) : "r"(a));
}
__device__ __forceinline__ void ldsm4t(uint4& d, unsigned a) {
    asm volatile("ldmatrix.sync.aligned.m8n8.x4.trans.shared.b16 {%0,%1,%2,%3}, [%4];"
                 : "=r"(d.x), "=r"(d.y), "=r"(d.z), "=r"(d.w) : "r"(a));
}
// NON-volatile: pure register op; lets ptxas schedule loads/MUFU across mmas.
__device__ __forceinline__ void mma16(float4& d, unsigned a0, unsigned a1, unsigned a2, unsigned a3,
                                      unsigned b0, unsigned b1) {
    asm("mma.sync.aligned.m16n8k16.row.col.f32.f16.f16.f32 "
        "{%0,%1,%2,%3},{%4,%5,%6,%7},{%8,%9},{%0,%1,%2,%3};"
        : "+f"(d.x), "+f"(d.y), "+f"(d.z), "+f"(d.w)
        : "r"(a0), "r"(a1), "r"(a2), "r"(a3), "r"(b0), "r"(b1));
}
__device__ __forceinline__ unsigned packh2(float lo, float hi) {
    unsigned r;
    asm("cvt.rn.f16x2.f32 %0, %1, %2;" : "=r"(r) : "f"(hi), "f"(lo));
    return r;
}

// ---------------- weight prep ----------------
__global__ void prep_kernel(const float* __restrict__ wb, const float* __restrict__ wq,
                            const float* __restrict__ wk, const float* __restrict__ wv,
                            const float* __restrict__ wg, const float* __restrict__ wo) {
    int idx = blockIdx.x * blockDim.x + threadIdx.x;
    if (idx < CIN * 512) {
        int c = idx >> 9, e = idx & 511;
        float val;
        if      (e < 128) val = wq[e * CIN + c] * 0.17677669529663687f;   // 1/sqrt(32)
        else if (e < 256) val = wk[(e - 128) * CIN + c];
        else if (e < 384) val = wv[(e - 256) * CIN + c];
        else              val = wg[(e - 384) * CIN + c];
        g_Wh[c][e] = __float2half(val);
    }
    if (idx < HH * CIN) {
        int h = idx >> 7, c = idx & 127;
        g_wbt[h][c] = wb[h * CIN + c];
    }
    if (idx < CIN * CIN) {
        int e = idx >> 7, c = idx & 127;
        g_Woh[e][c] = __float2half(wo[c * CIN + e]);
    }
}

// ---------------- fused LN + {q,k,v,gate} fp16-mma projection + tri-bias ----------------
struct LnSmem {
    __half xs[128][136];       // 128 data cols + 8 pad (row 272B)
    __half Bs[2][128][72];     // cp.async double-buffered 64-col weight chunks (row 144B)
    float mu[128], rs[128];
};

__global__ __launch_bounds__(256) void lnproj_kernel(const float* __restrict__ x,
                                                     const float* __restrict__ lnw,
                                                     const float* __restrict__ lnb,
                                                     const float* __restrict__ bg) {
    extern __shared__ char sraw[];
    LnSmem& S = *(LnSmem*)sraw;

    int t = threadIdx.x;
    int p0 = blockIdx.x * 128;
    int w = t >> 5, lane = t & 31;
    int gid = lane >> 2, tig = lane & 3;

    // kick off async load of weight chunk 0 (independent of LN work)
    for (int f = t; f < 1024; f += 256) {
        int k = f >> 3, c8 = (f & 7) * 8;
        cpa16(cvta_s(&S.Bs[0][k][c8]), &g_Wh[k][c8]);
    }
    CPA_COMMIT();

    // LN stats
    for (int rr = 0; rr < 16; rr++) {
        int r = w * 16 + rr;
        const float* xp = x + (size_t)(p0 + r) * CIN;
        float v0 = xp[lane], v1 = xp[lane + 32], v2 = xp[lane + 64], v3 = xp[lane + 96];
        float s = v0 + v1 + v2 + v3;
        float q = v0 * v0 + v1 * v1 + v2 * v2 + v3 * v3;
        #pragma unroll
        for (int off = 16; off; off >>= 1) {
            s += __shfl_down_sync(FULL, s, off);
            q += __shfl_down_sync(FULL, q, off);
        }
        if (lane == 0) {
            float m = s * (1.f / 128.f);
            S.mu[r] = m;
            S.rs[r] = rsqrtf(q * (1.f / 128.f) - m * m + 1e-5f);
        }
    }
    __syncthreads();

    // normalize -> fp16 xs
    for (int idx = t * 4; idx < 128 * 128; idx += 1024) {
        int r = idx >> 7, c = idx & 127;
        float4 xv = *(const float4*)(x + (size_t)(p0 + r) * CIN + c);
        float4 wv = *(const float4*)(lnw + c);
        float4 bv = *(const float4*)(lnb + c);
        float m = S.mu[r], rs = S.rs[r];
        *(__half2*)&S.xs[r][c]     = __floats2half2_rn((xv.x - m) * rs * wv.x + bv.x,
                                                       (xv.y - m) * rs * wv.y + bv.y);
        *(__half2*)&S.xs[r][c + 2] = __floats2half2_rn((xv.z - m) * rs * wv.z + bv.z,
                                                       (xv.w - m) * rs * wv.w + bv.w);
    }
    CPA_WAIT0();
    __syncthreads();

    int wm = w >> 1, wn = w & 1;              // warp tile: 32 rows x 32 cols of 64-chunk
    int m8 = lane >> 3, r8 = lane & 7;

    unsigned aBase = cvta_s(&S.xs[wm * 32 + (m8 & 1) * 8 + r8][(m8 >> 1) * 8]);
    unsigned bBase[2];
    bBase[0] = cvta_s(&S.Bs[0][(m8 & 1) * 8 + r8][wn * 32 + (m8 >> 1) * 8]);
    bBase[1] = cvta_s(&S.Bs[1][(m8 & 1) * 8 + r8][wn * 32 + (m8 >> 1) * 8]);

    int p_lo0 = p0 + wm * 32 + gid;
    int ii = p_lo0 >> 8;

    for (int nc = 0; nc < 8; nc++) {
        int cur = nc & 1;
        // async prefetch of next chunk overlaps with this chunk's mmas
        if (nc < 7) {
            for (int f = t; f < 1024; f += 256) {
                int k = f >> 3, c8 = (f & 7) * 8;
                cpa16(cvta_s(&S.Bs[cur ^ 1][k][c8]), &g_Wh[k][(nc + 1) * 64 + c8]);
            }
            CPA_COMMIT();
        }

        float4 acc[2][4];
        #pragma unroll
        for (int mt = 0; mt < 2; mt++)
            #pragma unroll
            for (int nt = 0; nt < 4; nt++) acc[mt][nt] = make_float4(0.f, 0.f, 0.f, 0.f);

        unsigned bb = bBase[cur];
        #pragma unroll
        for (int ks = 0; ks < 8; ks++) {
            uint4 A0, A1, B0, B1;
            ldsm4(A0, aBase + ks * 32);
            ldsm4(A1, aBase + ks * 32 + 4352);     // +16 rows (16*272B)
            ldsm4t(B0, bb + ks * 2304);            // +16 k-rows (16*144B)
            ldsm4t(B1, bb + ks * 2304 + 32);       // +16 n-cols
            mma16(acc[0][0], A0.x, A0.y, A0.z, A0.w, B0.x, B0.y);
            mma16(acc[0][1], A0.x, A0.y, A0.z, A0.w, B0.z, B0.w);
            mma16(acc[0][2], A0.x, A0.y, A0.z, A0.w, B1.x, B1.y);
            mma16(acc[0][3], A0.x, A0.y, A0.z, A0.w, B1.z, B1.w);
            mma16(acc[1][0], A1.x, A1.y, A1.z, A1.w, B0.x, B0.y);
            mma16(acc[1][1], A1.x, A1.y, A1.z, A1.w, B0.z, B0.w);
            mma16(acc[1][2], A1.x, A1.y, A1.z, A1.w, B1.x, B1.y);
            mma16(acc[1][3], A1.x, A1.y, A1.z, A1.w, B1.z, B1.w);
        }

        // epilogue to gmem
        int sel = nc >> 1;   // 0=q 1=k 2=v 3=gate
        #pragma unroll
        for (int mt = 0; mt < 2; mt++) {
            int p_lo = p_lo0 + mt * 16;
            int jj_lo = p_lo & 255, jj_hi = jj_lo + 8;
            #pragma unroll
            for (int nt = 0; nt < 4; nt++) {
                int e0 = nc * 64 + wn * 32 + nt * 8 + 2 * tig;
                int loc = e0 & 127;
                int hh = loc >> 5, d0 = loc & 31;
                float4 a = acc[mt][nt];
                if (sel == 0) {
                    *(__half2*)&g_q[ii][hh][jj_lo][d0] = __floats2half2_rn(a.x, a.y);
                    *(__half2*)&g_q[ii][hh][jj_hi][d0] = __floats2half2_rn(a.z, a.w);
                } else if (sel == 1) {
                    *(__half2*)&g_k[ii][hh][jj_lo][d0] = __floats2half2_rn(a.x, a.y);
                    *(__half2*)&g_k[ii][hh][jj_hi][d0] = __floats2half2_rn(a.z, a.w);
                } else if (sel == 2) {
                    *(__half2*)&g_v[ii][hh][jj_lo][d0] = __floats2half2_rn(a.x, a.y);
                    *(__half2*)&g_v[ii][hh][jj_hi][d0] = __floats2half2_rn(a.z, a.w);
                } else {
                    float2 bg2 = *(const float2*)(bg + loc);
                    float glx = 1.f / (1.f + __expf(-(a.x + bg2.x)));
                    float gly = 1.f / (1.f + __expf(-(a.y + bg2.y)));
                    float ghx = 1.f / (1.f + __expf(-(a.z + bg2.x)));
                    float ghy = 1.f / (1.f + __expf(-(a.w + bg2.y)));
                    *(__half2*)(g_gate + (size_t)p_lo * CIN + loc) = __floats2half2_rn(glx, gly);
                    *(__half2*)(g_gate + ((size_t)p_lo + 8) * CIN + loc) = __floats2half2_rn(ghx, ghy);
                }
            }
        }

        if (nc < 7) CPA_WAIT0();
        __syncthreads();
    }

    // triangle bias (fp16 out)
    for (int pp = t; pp < 512; pp += 256) {
        int rr = pp >> 2, hh = pp & 3;
        const float* wv = g_wbt[hh];
        float a = 0.f;
        #pragma unroll 16
        for (int c = 0; c < 128; c += 2) {
            float2 fx = __half22float2(*(__half2*)&S.xs[rr][c]);
            a += fx.x * wv[c] + fx.y * wv[c + 1];
        }
        int p = p0 + rr;
        g_tbh[hh][p >> 8][p & 255] = __float2half(a);
    }
}

// ---------------- fp16-mma flash attention + gating ----------------
// CTA = (i, h): 256 threads, 8 warps, warp owns 32 queries. K/V staged ONCE.
struct AttnSmem {
    __half Qs[256][40];
    __half Ks[256][40];
    __half Vs[256][40];
    float mbs[256];
};

__global__ __launch_bounds__(256, 2) void attn_kernel(const float* __restrict__ mask) {
    extern __shared__ char sraw[];
    AttnSmem& S = *(AttnSmem*)sraw;

    int bid = blockIdx.x;
    int i = bid >> 2;
    int h = bid & 3;
    int t = threadIdx.x;
    int w = t >> 5, lane = t & 31;
    int gid = lane >> 2, tig = lane & 3;

    const __half* qg = &g_q[i][h][0][0];
    const __half* kg = &g_k[i][h][0][0];
    const __half* vg = &g_v[i][h][0][0];
    for (int f = t; f < 1024; f += 256) {
        int r = f >> 2, c8 = (f & 3) * 8;
        cpa16(cvta_s(&S.Qs[r][c8]), qg + r * 32 + c8);
        cpa16(cvta_s(&S.Ks[r][c8]), kg + r * 32 + c8);
        cpa16(cvta_s(&S.Vs[r][c8]), vg + r * 32 + c8);
    }
    CPA_COMMIT();
    S.mbs[t] = 1e9f * (mask[i * NN + t] - 1.0f);
    CPA_WAIT0();
    __syncthreads();

    int m8 = lane >> 3, r8 = lane & 7;

    // Q fragments: warp rows w*32..w*32+31, 2 m-tiles x 2 ksteps
    unsigned qA = cvta_s(&S.Qs[w * 32 + (m8 & 1) * 8 + r8][(m8 >> 1) * 8]);
    uint4 aq[2][2];
    #pragma unroll
    for (int mt = 0; mt < 2; mt++) {
        ldsm4(aq[mt][0], qA + mt * 1280);        // +16 rows (16*80B)
        ldsm4(aq[mt][1], qA + mt * 1280 + 32);   // +16 cols (d16-31)
    }

    unsigned kA = cvta_s(&S.Ks[(m8 & 1) * 8 + r8][(m8 >> 1) * 8]);
    unsigned vA = cvta_s(&S.Vs[(m8 & 1) * 8 + r8][(m8 >> 1) * 8]);

    float4 oacc[2][4];
    #pragma unroll
    for (int mt = 0; mt < 2; mt++)
        #pragma unroll
        for (int n = 0; n < 4; n++) oacc[mt][n] = make_float4(0.f, 0.f, 0.f, 0.f);
    float l_lo[2] = {0.f, 0.f}, l_hi[2] = {0.f, 0.f};

    const __half* tb_base = &g_tbh[h][0][0];
    int q_row0 = w * 32 + gid;     // mt adds +16, hi adds +8

    for (int kb = 0; kb < 8; kb++) {
        int kbase = kb * 32;

        // S = Q @ K^T for 32 keys (K [key][d] col-major kxn -> NON-trans ldsm)
        float4 s[2][4];
        #pragma unroll
        for (int mt = 0; mt < 2; mt++)
            #pragma unroll
            for (int nt = 0; nt < 4; nt++) s[mt][nt] = make_float4(0.f, 0.f, 0.f, 0.f);

        #pragma unroll
        for (int ntp = 0; ntp < 2; ntp++) {
            unsigned ka = kA + (kbase + ntp * 16) * 80;
            uint4 B0, B1;
            ldsm4(B0, ka);
            ldsm4(B1, ka + 32);
            #pragma unroll
            for (int mt = 0; mt < 2; mt++) {
                mma16(s[mt][2 * ntp],     aq[mt][0].x, aq[mt][0].y, aq[mt][0].z, aq[mt][0].w, B0.x, B0.z);
                mma16(s[mt][2 * ntp],     aq[mt][1].x, aq[mt][1].y, aq[mt][1].z, aq[mt][1].w, B1.x, B1.z);
                mma16(s[mt][2 * ntp + 1], aq[mt][0].x, aq[mt][0].y, aq[mt][0].z, aq[mt][0].w, B0.y, B0.w);
                mma16(s[mt][2 * ntp + 1], aq[mt][1].x, aq[mt][1].y, aq[mt][1].z, aq[mt][1].w, B1.y, B1.w);
            }
        }

        // V fragments hoisted: independent of S, LDSM latency hides under exp below
        uint4 Vf[2][2];
        #pragma unroll
        for (int ktp = 0; ktp < 2; ktp++) {
            unsigned va = vA + (kbase + ktp * 16) * 80;
            ldsm4t(Vf[ktp][0], va);
            ldsm4t(Vf[ktp][1], va + 32);
        }

        // bias + exp + pack to fp16 A-fragments
        unsigned pa[2][2][4];
        #pragma unroll
        for (int mt = 0; mt < 2; mt++) {
            const __half* tb_lo = tb_base + (q_row0 + mt * 16) * NN;
            const __half* tb_hi = tb_lo + 8 * NN;
            #pragma unroll
            for (int nt = 0; nt < 4; nt++) {
                int c0 = kbase + nt * 8 + 2 * tig;
                float2 tl = __half22float2(*(const __half2*)(tb_lo + c0));
                float2 th = __half22float2(*(const __half2*)(tb_hi + c0));
                float mb0 = S.mbs[c0], mb1 = S.mbs[c0 + 1];
                float px = __expf(s[mt][nt].x + tl.x + mb0);
                float py = __expf(s[mt][nt].y + tl.y + mb1);
                float pz = __expf(s[mt][nt].z + th.x + mb0);
                float pw = __expf(s[mt][nt].w + th.y + mb1);
                l_lo[mt] += px + py;
                l_hi[mt] += pz + pw;
                int ktp = nt >> 1;
                if (!(nt & 1)) {
                    pa[mt][ktp][0] = packh2(px, py);
                    pa[mt][ktp][1] = packh2(pz, pw);
                } else {
                    pa[mt][ktp][2] = packh2(px, py);
                    pa[mt][ktp][3] = packh2(pz, pw);
                }
            }
        }

        // O += P @ V
        #pragma unroll
        for (int ktp = 0; ktp < 2; ktp++) {
            #pragma unroll
            for (int mt = 0; mt < 2; mt++) {
                mma16(oacc[mt][0], pa[mt][ktp][0], pa[mt][ktp][1], pa[mt][ktp][2], pa[mt][ktp][3], Vf[ktp][0].x, Vf[ktp][0].y);
                mma16(oacc[mt][1], pa[mt][ktp][0], pa[mt][ktp][1], pa[mt][ktp][2], pa[mt][ktp][3], Vf[ktp][0].z, Vf[ktp][0].w);
                mma16(oacc[mt][2], pa[mt][ktp][0], pa[mt][ktp][1], pa[mt][ktp][2], pa[mt][ktp][3], Vf[ktp][1].x, Vf[ktp][1].y);
                mma16(oacc[mt][3], pa[mt][ktp][0], pa[mt][ktp][1], pa[mt][ktp][2], pa[mt][ktp][3], Vf[ktp][1].z, Vf[ktp][1].w);
            }
        }
    }

    // finalize + gated store
    #pragma unroll
    for (int mt = 0; mt < 2; mt++) {
        float ll = l_lo[mt], lh = l_hi[mt];
        ll += __shfl_xor_sync(FULL, ll, 1);
        ll += __shfl_xor_sync(FULL, ll, 2);
        lh += __shfl_xor_sync(FULL, lh, 1);
        lh += __shfl_xor_sync(FULL, lh, 2);
        float inv_lo = 1.f / ll, inv_hi = 1.f / lh;

        int q_lo = q_row0 + mt * 16, q_hi = q_lo + 8;
        size_t base_lo = ((size_t)(i * NN + q_lo)) * CIN + h * DD;
        size_t base_hi = ((size_t)(i * NN + q_hi)) * CIN + h * DD;
        #pragma unroll
        for (int ntd = 0; ntd < 4; ntd++) {
            int d0 = ntd * 8 + 2 * tig;
            float2 gl = __half22float2(*(__half2*)(g_gate + base_lo + d0));
            float2 gh = __half22float2(*(__half2*)(g_gate + base_hi + d0));
            *(__half2*)(g_o + base_lo + d0) =
                __floats2half2_rn(oacc[mt][ntd].x * inv_lo * gl.x, oacc[mt][ntd].y * inv_lo * gl.y);
            *(__half2*)(g_o + base_hi + d0) =
                __floats2half2_rn(oacc[mt][ntd].z * inv_hi * gh.x, oacc[mt][ntd].w * inv_hi * gh.y);
        }
    }
}

// ---------------- fp16-mma output projection ----------------
struct OutSmem {
    __half os[128][136];
    __half Ws[128][136];
};

__global__ __launch_bounds__(256) void outproj_kernel(float* __restrict__ out,
                                                      const float* __restrict__ bo) {
    extern __shared__ char sraw[];
    OutSmem& S = *(OutSmem*)sraw;

    int t = threadIdx.x;
    int p0 = blockIdx.x * 128;
    int w = t >> 5, lane = t & 31;
    int gid = lane >> 2, tig = lane & 3;

    for (int f = t; f < 2048; f += 256) {
        int r = f >> 4, c8 = (f & 15) * 8;
        cpa16(cvta_s(&S.os[r][c8]), g_o + (size_t)(p0 + r) * CIN + c8);
        cpa16(cvta_s(&S.Ws[r][c8]), &g_Woh[r][c8]);
    }
    CPA_COMMIT();
    CPA_WAIT0();
    __syncthreads();

    int wm = w >> 1, wn = w & 1;           // warp tile 32 rows x 64 cols
    int m8 = lane >> 3, r8 = lane & 7;

    unsigned aBase = cvta_s(&S.os[wm * 32 + (m8 & 1) * 8 + r8][(m8 >> 1) * 8]);
    unsigned bBase = cvta_s(&S.Ws[(m8 & 1) * 8 + r8][wn * 64 + (m8 >> 1) * 8]);

    float4 acc[2][8];
    #pragma unroll
    for (int mt = 0; mt < 2; mt++)
        #pragma unroll
        for (int nt = 0; nt < 8; nt++) acc[mt][nt] = make_float4(0.f, 0.f, 0.f, 0.f);

    #pragma unroll
    for (int ks = 0; ks < 8; ks++) {
        uint4 A0, A1;
        ldsm4(A0, aBase + ks * 32);
        ldsm4(A1, aBase + ks * 32 + 4352);   // +16 rows (16*272B)
        uint4 B[4];
        #pragma unroll
        for (int ngp = 0; ngp < 4; ngp++) ldsm4t(B[ngp], bBase + ks * 4352 + ngp * 32);
        #pragma unroll
        for (int ngp = 0; ngp < 4; ngp++) {
            mma16(acc[0][2 * ngp],     A0.x, A0.y, A0.z, A0.w, B[ngp].x, B[ngp].y);
            mma16(acc[0][2 * ngp + 1], A0.x, A0.y, A0.z, A0.w, B[ngp].z, B[ngp].w);
            mma16(acc[1][2 * ngp],     A1.x, A1.y, A1.z, A1.w, B[ngp].x, B[ngp].y);
            mma16(acc[1][2 * ngp + 1], A1.x, A1.y, A1.z, A1.w, B[ngp].z, B[ngp].w);
        }
    }

    #pragma unroll
    for (int mt = 0; mt < 2; mt++) {
        int p_lo = p0 + wm * 32 + mt * 16 + gid;
        int p_hi = p_lo + 8;
        #pragma unroll
        for (int nt = 0; nt < 8; nt++) {
            int c0 = wn * 64 + nt * 8 + 2 * tig;
            float2 bo2 = *(const float2*)(bo + c0);
            *(float2*)(out + (size_t)p_lo * CIN + c0) =
                make_float2(acc[mt][nt].x + bo2.x, acc[mt][nt].y + bo2.y);
            *(float2*)(out + (size_t)p_hi * CIN + c0) =
                make_float2(acc[mt][nt].z + bo2.x, acc[mt][nt].w + bo2.y);
        }
    }
}

extern "C" void kernel_launch(void* const* d_in, const int* in_sizes, int n_in,
                              void* d_out, int out_size) {
    (void)in_sizes; (void)n_in; (void)out_size;
    const float* x    = (const float*)d_in[0];
    const float* mask = (const float*)d_in[1];
    const float* lnw  = (const float*)d_in[2];
    const float* lnb  = (const float*)d_in[3];
    const float* wb   = (const float*)d_in[4];
    const float* wq   = (const float*)d_in[5];
    const float* wk   = (const float*)d_in[6];
    const float* wv   = (const float*)d_in[7];
    const float* wg   = (const float*)d_in[8];
    const float* bg   = (const float*)d_in[9];
    const float* wo   = (const float*)d_in[10];
    const float* bo   = (const float*)d_in[11];
    float* out = (float*)d_out;

    cudaFuncSetAttribute(lnproj_kernel,  cudaFuncAttributeMaxDynamicSharedMemorySize, (int)sizeof(LnSmem));
    cudaFuncSetAttribute(attn_kernel,    cudaFuncAttributeMaxDynamicSharedMemorySize, (int)sizeof(AttnSmem));
    cudaFuncSetAttribute(outproj_kernel, cudaFuncAttributeMaxDynamicSharedMemorySize, (int)sizeof(OutSmem));

    prep_kernel<<<256, 256>>>(wb, wq, wk, wv, wg, wo);
    lnproj_kernel<<<512, 256, sizeof(LnSmem)>>>(x, lnw, lnb, bg);
    attn_kernel<<<1024, 256, sizeof(AttnSmem)>>>(mask);
    outproj_kernel<<<512, 256, sizeof(OutSmem)>>>(out, bo);
}

// round 12
// speedup vs baseline: 1.1478x; 1.0025x over previous
#include <cuda_runtime.h>
#include <cuda_fp16.h>
#include <math.h>

#define NN   256
#define CIN  128
#define HH   4
#define DD   32
#define NPOS (NN*NN)
#define FULL 0xffffffffu
#define LOG2E 1.4426950408889634f

// ---------------- scratch (device globals) ----------------
__device__ __half g_Wh[CIN][512];          // [c][e] fp16: e<128 wq*scale*log2e, <256 wk, <384 wv, <512 wg
__device__ float  g_wbt[HH][CIN];          // tri-bias weights f32 (x log2e)
__device__ __half g_Woh[CIN][CIN];         // [e][c] = w_o[c][e] fp16
__device__ __half g_q[NN][HH][NN][DD];
__device__ __half g_k[NN][HH][NN][DD];
__device__ __half g_v[NN][HH][NN][DD];
__device__ __half g_gate[(size_t)NPOS*CIN];
__device__ __half g_tbh[HH][NN][NN];       // [h][query][key] fp16, pre-scaled by log2e
__device__ __half g_o[(size_t)NPOS*CIN];

// ---------------- helpers ----------------
__device__ __forceinline__ unsigned cvta_s(const void* p) {
    return (unsigned)__cvta_generic_to_shared(p);
}
__device__ __forceinline__ void cpa16(unsigned dst, const void* src) {
    asm volatile("cp.async.cg.shared.global [%0], [%1], 16;" :: "r"(dst), "l"(src) : "memory");
}
#define CPA_COMMIT() asm volatile("cp.async.commit_group;" ::: "memory")
#define CPA_WAIT0()  asm volatile("cp.async.wait_group 0;" ::: "memory")

__device__ __forceinline__ void ldsm4(uint4& d, unsigned a) {
    asm volatile("ldmatrix.sync.aligned.m8n8.x4.shared.b16 {%0,%1,%2,%3}, [%4];"
                 : "=r"(d.x), "=r"(d.y), "=r"(d.z), "=r"(d.w) : "r"(a));
}
__device__ __forceinline__ void ldsm4t(uint4& d, unsigned a) {
    asm volatile("ldmatrix.sync.aligned.m8n8.x4.trans.shared.b16 {%0,%1,%2,%3}, [%4];"
                 : "=r"(d.x), "=r"(d.y), "=r"(d.z), "=r"(d.w) : "r"(a));
}
// NON-volatile: lets ptxas schedule loads/MUFU across mmas.
__device__ __forceinline__ void mma16(float4& d, unsigned a0, unsigned a1, unsigned a2, unsigned a3,
                                      unsigned b0, unsigned b1) {
    asm("mma.sync.aligned.m16n8k16.row.col.f32.f16.f16.f32 "
        "{%0,%1,%2,%3},{%4,%5,%6,%7},{%8,%9},{%0,%1,%2,%3};"
        : "+f"(d.x), "+f"(d.y), "+f"(d.z), "+f"(d.w)
        : "r"(a0), "r"(a1), "r"(a2), "r"(a3), "r"(b0), "r"(b1));
}
__device__ __forceinline__ unsigned packh2(float lo, float hi) {
    unsigned r;
    asm("cvt.rn.f16x2.f32 %0, %1, %2;" : "=r"(r) : "f"(hi), "f"(lo));
    return r;
}
// raw 2^x (log2e pre-folded into scores)
__device__ __forceinline__ float ex2f(float x) {
    float r;
    asm("ex2.approx.f32 %0, %1;" : "=f"(r) : "f"(x));
    return r;
}

// ---------------- weight prep ----------------
__global__ void prep_kernel(const float* __restrict__ wb, const float* __restrict__ wq,
                            const float* __restrict__ wk, const float* __restrict__ wv,
                            const float* __restrict__ wg, const float* __restrict__ wo) {
    int idx = blockIdx.x * blockDim.x + threadIdx.x;
    if (idx < CIN * 512) {
        int c = idx >> 9, e = idx & 511;
        float val;
        if      (e < 128) val = wq[e * CIN + c] * (0.17677669529663687f * LOG2E);
        else if (e < 256) val = wk[(e - 128) * CIN + c];
        else if (e < 384) val = wv[(e - 256) * CIN + c];
        else              val = wg[(e - 384) * CIN + c];
        g_Wh[c][e] = __float2half(val);
    }
    if (idx < HH * CIN) {
        int h = idx >> 7, c = idx & 127;
        g_wbt[h][c] = wb[h * CIN + c] * LOG2E;
    }
    if (idx < CIN * CIN) {
        int e = idx >> 7, c = idx & 127;
        g_Woh[e][c] = __float2half(wo[c * CIN + e]);
    }
}

// ---------------- fused LN + {q,k,v,gate} fp16-mma projection + tri-bias ----------------
struct LnSmem {
    __half xs[128][136];       // 128 data cols + 8 pad (row 272B)
    __half Bs[2][128][72];     // cp.async double-buffered 64-col weight chunks (row 144B)
    float mu[128], rs[128];
};

__global__ __launch_bounds__(256, 3) void lnproj_kernel(const float* __restrict__ x,
                                                        const float* __restrict__ lnw,
                                                        const float* __restrict__ lnb,
                                                        const float* __restrict__ bg) {
    extern __shared__ char sraw[];
    LnSmem& S = *(LnSmem*)sraw;

    int t = threadIdx.x;
    int p0 = blockIdx.x * 128;
    int w = t >> 5, lane = t & 31;
    int gid = lane >> 2, tig = lane & 3;

    // kick off async load of weight chunk 0 (independent of LN work)
    for (int f = t; f < 1024; f += 256) {
        int k = f >> 3, c8 = (f & 7) * 8;
        cpa16(cvta_s(&S.Bs[0][k][c8]), &g_Wh[k][c8]);
    }
    CPA_COMMIT();

    // LN stats
    for (int rr = 0; rr < 16; rr++) {
        int r = w * 16 + rr;
        const float* xp = x + (size_t)(p0 + r) * CIN;
        float v0 = xp[lane], v1 = xp[lane + 32], v2 = xp[lane + 64], v3 = xp[lane + 96];
        float s = v0 + v1 + v2 + v3;
        float q = v0 * v0 + v1 * v1 + v2 * v2 + v3 * v3;
        #pragma unroll
        for (int off = 16; off; off >>= 1) {
            s += __shfl_down_sync(FULL, s, off);
            q += __shfl_down_sync(FULL, q, off);
        }
        if (lane == 0) {
            float m = s * (1.f / 128.f);
            S.mu[r] = m;
            S.rs[r] = rsqrtf(q * (1.f / 128.f) - m * m + 1e-5f);
        }
    }
    __syncthreads();

    // normalize -> fp16 xs
    for (int idx = t * 4; idx < 128 * 128; idx += 1024) {
        int r = idx >> 7, c = idx & 127;
        float4 xv = *(const float4*)(x + (size_t)(p0 + r) * CIN + c);
        float4 wv = *(const float4*)(lnw + c);
        float4 bv = *(const float4*)(lnb + c);
        float m = S.mu[r], rs = S.rs[r];
        *(__half2*)&S.xs[r][c]     = __floats2half2_rn((xv.x - m) * rs * wv.x + bv.x,
                                                       (xv.y - m) * rs * wv.y + bv.y);
        *(__half2*)&S.xs[r][c + 2] = __floats2half2_rn((xv.z - m) * rs * wv.z + bv.z,
                                                       (xv.w - m) * rs * wv.w + bv.w);
    }
    CPA_WAIT0();
    __syncthreads();

    int wm = w >> 1, wn = w & 1;              // warp tile: 32 rows x 32 cols of 64-chunk
    int m8 = lane >> 3, r8 = lane & 7;

    unsigned aBase = cvta_s(&S.xs[wm * 32 + (m8 & 1) * 8 + r8][(m8 >> 1) * 8]);
    unsigned bBase[2];
    bBase[0] = cvta_s(&S.Bs[0][(m8 & 1) * 8 + r8][wn * 32 + (m8 >> 1) * 8]);
    bBase[1] = cvta_s(&S.Bs[1][(m8 & 1) * 8 + r8][wn * 32 + (m8 >> 1) * 8]);

    int p_lo0 = p0 + wm * 32 + gid;
    int ii = p_lo0 >> 8;

    for (int nc = 0; nc < 8; nc++) {
        int cur = nc & 1;
        // async prefetch of next chunk overlaps with this chunk's mmas
        if (nc < 7) {
            for (int f = t; f < 1024; f += 256) {
                int k = f >> 3, c8 = (f & 7) * 8;
                cpa16(cvta_s(&S.Bs[cur ^ 1][k][c8]), &g_Wh[k][(nc + 1) * 64 + c8]);
            }
            CPA_COMMIT();
        }

        float4 acc[2][4];
        #pragma unroll
        for (int mt = 0; mt < 2; mt++)
            #pragma unroll
            for (int nt = 0; nt < 4; nt++) acc[mt][nt] = make_float4(0.f, 0.f, 0.f, 0.f);

        unsigned bb = bBase[cur];
        #pragma unroll
        for (int ks = 0; ks < 8; ks++) {
            uint4 A0, A1, B0, B1;
            ldsm4(A0, aBase + ks * 32);
            ldsm4(A1, aBase + ks * 32 + 4352);     // +16 rows (16*272B)
            ldsm4t(B0, bb + ks * 2304);            // +16 k-rows (16*144B)
            ldsm4t(B1, bb + ks * 2304 + 32);       // +16 n-cols
            mma16(acc[0][0], A0.x, A0.y, A0.z, A0.w, B0.x, B0.y);
            mma16(acc[0][1], A0.x, A0.y, A0.z, A0.w, B0.z, B0.w);
            mma16(acc[0][2], A0.x, A0.y, A0.z, A0.w, B1.x, B1.y);
            mma16(acc[0][3], A0.x, A0.y, A0.z, A0.w, B1.z, B1.w);
            mma16(acc[1][0], A1.x, A1.y, A1.z, A1.w, B0.x, B0.y);
            mma16(acc[1][1], A1.x, A1.y, A1.z, A1.w, B0.z, B0.w);
            mma16(acc[1][2], A1.x, A1.y, A1.z, A1.w, B1.x, B1.y);
            mma16(acc[1][3], A1.x, A1.y, A1.z, A1.w, B1.z, B1.w);
        }

        // epilogue to gmem
        int sel = nc >> 1;   // 0=q 1=k 2=v 3=gate
        #pragma unroll
        for (int mt = 0; mt < 2; mt++) {
            int p_lo = p_lo0 + mt * 16;
            int jj_lo = p_lo & 255, jj_hi = jj_lo + 8;
            #pragma unroll
            for (int nt = 0; nt < 4; nt++) {
                int e0 = nc * 64 + wn * 32 + nt * 8 + 2 * tig;
                int loc = e0 & 127;
                int hh = loc >> 5, d0 = loc & 31;
                float4 a = acc[mt][nt];
                if (sel == 0) {
                    *(__half2*)&g_q[ii][hh][jj_lo][d0] = __floats2half2_rn(a.x, a.y);
                    *(__half2*)&g_q[ii][hh][jj_hi][d0] = __floats2half2_rn(a.z, a.w);
                } else if (sel == 1) {
                    *(__half2*)&g_k[ii][hh][jj_lo][d0] = __floats2half2_rn(a.x, a.y);
                    *(__half2*)&g_k[ii][hh][jj_hi][d0] = __floats2half2_rn(a.z, a.w);
                } else if (sel == 2) {
                    *(__half2*)&g_v[ii][hh][jj_lo][d0] = __floats2half2_rn(a.x, a.y);
                    *(__half2*)&g_v[ii][hh][jj_hi][d0] = __floats2half2_rn(a.z, a.w);
                } else {
                    float2 bg2 = *(const float2*)(bg + loc);
                    float glx = 1.f / (1.f + __expf(-(a.x + bg2.x)));
                    float gly = 1.f / (1.f + __expf(-(a.y + bg2.y)));
                    float ghx = 1.f / (1.f + __expf(-(a.z + bg2.x)));
                    float ghy = 1.f / (1.f + __expf(-(a.w + bg2.y)));
                    *(__half2*)(g_gate + (size_t)p_lo * CIN + loc) = __floats2half2_rn(glx, gly);
                    *(__half2*)(g_gate + ((size_t)p_lo + 8) * CIN + loc) = __floats2half2_rn(ghx, ghy);
                }
            }
        }

        if (nc < 7) CPA_WAIT0();
        __syncthreads();
    }

    // triangle bias (fp16 out, pre-scaled by log2e via g_wbt)
    for (int pp = t; pp < 512; pp += 256) {
        int rr = pp >> 2, hh = pp & 3;
        const float* wv = g_wbt[hh];
        float a = 0.f;
        #pragma unroll 16
        for (int c = 0; c < 128; c += 2) {
            float2 fx = __half22float2(*(__half2*)&S.xs[rr][c]);
            a += fx.x * wv[c] + fx.y * wv[c + 1];
        }
        int p = p0 + rr;
        g_tbh[hh][p >> 8][p & 255] = __float2half(a);
    }
}

// ---------------- fp16-mma flash attention + gating ----------------
// CTA = (i, h): 256 threads, 8 warps, warp owns 32 queries. K/V staged ONCE.
struct AttnSmem {
    __half Qs[256][40];
    __half Ks[256][40];
    __half Vs[256][40];
    float mbs[256];
};

__global__ __launch_bounds__(256, 2) void attn_kernel(const float* __restrict__ mask) {
    extern __shared__ char sraw[];
    AttnSmem& S = *(AttnSmem*)sraw;

    int bid = blockIdx.x;
    int i = bid >> 2;
    int h = bid & 3;
    int t = threadIdx.x;
    int w = t >> 5, lane = t & 31;
    int gid = lane >> 2, tig = lane & 3;

    const __half* qg = &g_q[i][h][0][0];
    const __half* kg = &g_k[i][h][0][0];
    const __half* vg = &g_v[i][h][0][0];
    for (int f = t; f < 1024; f += 256) {
        int r = f >> 2, c8 = (f & 3) * 8;
        cpa16(cvta_s(&S.Qs[r][c8]), qg + r * 32 + c8);
        cpa16(cvta_s(&S.Ks[r][c8]), kg + r * 32 + c8);
        cpa16(cvta_s(&S.Vs[r][c8]), vg + r * 32 + c8);
    }
    CPA_COMMIT();
    S.mbs[t] = (1e9f * LOG2E) * (mask[i * NN + t] - 1.0f);
    CPA_WAIT0();
    __syncthreads();

    int m8 = lane >> 3, r8 = lane & 7;

    // Q fragments: warp rows w*32..w*32+31, 2 m-tiles x 2 ksteps
    unsigned qA = cvta_s(&S.Qs[w * 32 + (m8 & 1) * 8 + r8][(m8 >> 1) * 8]);
    uint4 aq[2][2];
    #pragma unroll
    for (int mt = 0; mt < 2; mt++) {
        ldsm4(aq[mt][0], qA + mt * 1280);        // +16 rows (16*80B)
        ldsm4(aq[mt][1], qA + mt * 1280 + 32);   // +16 cols (d16-31)
    }

    unsigned kA = cvta_s(&S.Ks[(m8 & 1) * 8 + r8][(m8 >> 1) * 8]);
    unsigned vA = cvta_s(&S.Vs[(m8 & 1) * 8 + r8][(m8 >> 1) * 8]);

    float4 oacc[2][4];
    #pragma unroll
    for (int mt = 0; mt < 2; mt++)
        #pragma unroll
        for (int n = 0; n < 4; n++) oacc[mt][n] = make_float4(0.f, 0.f, 0.f, 0.f);
    float l_lo[2] = {0.f, 0.f}, l_hi[2] = {0.f, 0.f};

    const __half* tb_base = &g_tbh[h][0][0];
    int q_row0 = w * 32 + gid;     // mt adds +16, hi adds +8

    for (int kb = 0; kb < 8; kb++) {
        int kbase = kb * 32;

        // S = Q @ K^T for 32 keys (K [key][d] col-major kxn -> NON-trans ldsm)
        float4 s[2][4];
        #pragma unroll
        for (int mt = 0; mt < 2; mt++)
            #pragma unroll
            for (int nt = 0; nt < 4; nt++) s[mt][nt] = make_float4(0.f, 0.f, 0.f, 0.f);

        #pragma unroll
        for (int ntp = 0; ntp < 2; ntp++) {
            unsigned ka = kA + (kbase + ntp * 16) * 80;
            uint4 B0, B1;
            ldsm4(B0, ka);
            ldsm4(B1, ka + 32);
            #pragma unroll
            for (int mt = 0; mt < 2; mt++) {
                mma16(s[mt][2 * ntp],     aq[mt][0].x, aq[mt][0].y, aq[mt][0].z, aq[mt][0].w, B0.x, B0.z);
                mma16(s[mt][2 * ntp],     aq[mt][1].x, aq[mt][1].y, aq[mt][1].z, aq[mt][1].w, B1.x, B1.z);
                mma16(s[mt][2 * ntp + 1], aq[mt][0].x, aq[mt][0].y, aq[mt][0].z, aq[mt][0].w, B0.y, B0.w);
                mma16(s[mt][2 * ntp + 1], aq[mt][1].x, aq[mt][1].y, aq[mt][1].z, aq[mt][1].w, B1.y, B1.w);
            }
        }

        // V fragments hoisted: independent of S, LDSM latency hides under exp below
        uint4 Vf[2][2];
        #pragma unroll
        for (int ktp = 0; ktp < 2; ktp++) {
            unsigned va = vA + (kbase + ktp * 16) * 80;
            ldsm4t(Vf[ktp][0], va);
            ldsm4t(Vf[ktp][1], va + 32);
        }

        // bias + 2^x + pack to fp16 A-fragments (log2e pre-folded)
        unsigned pa[2][2][4];
        #pragma unroll
        for (int mt = 0; mt < 2; mt++) {
            const __half* tb_lo = tb_base + (q_row0 + mt * 16) * NN;
            const __half* tb_hi = tb_lo + 8 * NN;
            #pragma unroll
            for (int nt = 0; nt < 4; nt++) {
                int c0 = kbase + nt * 8 + 2 * tig;
                float2 tl = __half22float2(*(const __half2*)(tb_lo + c0));
                float2 th = __half22float2(*(const __half2*)(tb_hi + c0));
                float mb0 = S.mbs[c0], mb1 = S.mbs[c0 + 1];
                float px = ex2f(s[mt][nt].x + tl.x + mb0);
                float py = ex2f(s[mt][nt].y + tl.y + mb1);
                float pz = ex2f(s[mt][nt].z + th.x + mb0);
                float pw = ex2f(s[mt][nt].w + th.y + mb1);
                l_lo[mt] += px + py;
                l_hi[mt] += pz + pw;
                int ktp = nt >> 1;
                if (!(nt & 1)) {
                    pa[mt][ktp][0] = packh2(px, py);
                    pa[mt][ktp][1] = packh2(pz, pw);
                } else {
                    pa[mt][ktp][2] = packh2(px, py);
                    pa[mt][ktp][3] = packh2(pz, pw);
                }
            }
        }

        // O += P @ V
        #pragma unroll
        for (int ktp = 0; ktp < 2; ktp++) {
            #pragma unroll
            for (int mt = 0; mt < 2; mt++) {
                mma16(oacc[mt][0], pa[mt][ktp][0], pa[mt][ktp][1], pa[mt][ktp][2], pa[mt][ktp][3], Vf[ktp][0].x, Vf[ktp][0].y);
                mma16(oacc[mt][1], pa[mt][ktp][0], pa[mt][ktp][1], pa[mt][ktp][2], pa[mt][ktp][3], Vf[ktp][0].z, Vf[ktp][0].w);
                mma16(oacc[mt][2], pa[mt][ktp][0], pa[mt][ktp][1], pa[mt][ktp][2], pa[mt][ktp][3], Vf[ktp][1].x, Vf[ktp][1].y);
                mma16(oacc[mt][3], pa[mt][ktp][0], pa[mt][ktp][1], pa[mt][ktp][2], pa[mt][ktp][3], Vf[ktp][1].z, Vf[ktp][1].w);
            }
        }
    }

    // finalize + gated store
    #pragma unroll
    for (int mt = 0; mt < 2; mt++) {
        float ll = l_lo[mt], lh = l_hi[mt];
        ll += __shfl_xor_sync(FULL, ll, 1);
        ll += __shfl_xor_sync(FULL, ll, 2);
        lh += __shfl_xor_sync(FULL, lh, 1);
        lh += __shfl_xor_sync(FULL, lh, 2);
        float inv_lo = 1.f / ll, inv_hi = 1.f / lh;

        int q_lo = q_row0 + mt * 16, q_hi = q_lo + 8;
        size_t base_lo = ((size_t)(i * NN + q_lo)) * CIN + h * DD;
        size_t base_hi = ((size_t)(i * NN + q_hi)) * CIN + h * DD;
        #pragma unroll
        for (int ntd = 0; ntd < 4; ntd++) {
            int d0 = ntd * 8 + 2 * tig;
            float2 gl = __half22float2(*(__half2*)(g_gate + base_lo + d0));
            float2 gh = __half22float2(*(__half2*)(g_gate + base_hi + d0));
            *(__half2*)(g_o + base_lo + d0) =
                __floats2half2_rn(oacc[mt][ntd].x * inv_lo * gl.x, oacc[mt][ntd].y * inv_lo * gl.y);
            *(__half2*)(g_o + base_hi + d0) =
                __floats2half2_rn(oacc[mt][ntd].z * inv_hi * gh.x, oacc[mt][ntd].w * inv_hi * gh.y);
        }
    }
}

// ---------------- fp16-mma output projection: split-N (128 rows x 64 cols per CTA) ----------------
struct OutSmem {
    __half os[128][136];    // full 128-col activations
    __half Ws[128][72];     // this CTA's 64 weight cols
};

__global__ __launch_bounds__(256, 3) void outproj_kernel(float* __restrict__ out,
                                                         const float* __restrict__ bo) {
    extern __shared__ char sraw[];
    OutSmem& S = *(OutSmem*)sraw;

    int bid = blockIdx.x;
    int p0 = (bid >> 1) * 128;
    int n0 = (bid & 1) * 64;
    int t = threadIdx.x;
    int w = t >> 5, lane = t & 31;
    int gid = lane >> 2, tig = lane & 3;

    for (int f = t; f < 2048; f += 256) {
        int r = f >> 4, c8 = (f & 15) * 8;
        cpa16(cvta_s(&S.os[r][c8]), g_o + (size_t)(p0 + r) * CIN + c8);
    }
    for (int f = t; f < 1024; f += 256) {
        int r = f >> 3, c8 = (f & 7) * 8;
        cpa16(cvta_s(&S.Ws[r][c8]), &g_Woh[r][n0 + c8]);
    }
    CPA_COMMIT();
    CPA_WAIT0();
    __syncthreads();

    int wm = w >> 1, wn = w & 1;           // warp tile 32 rows x 32 cols
    int m8 = lane >> 3, r8 = lane & 7;

    unsigned aBase = cvta_s(&S.os[wm * 32 + (m8 & 1) * 8 + r8][(m8 >> 1) * 8]);
    unsigned bBase = cvta_s(&S.Ws[(m8 & 1) * 8 + r8][wn * 32 + (m8 >> 1) * 8]);

    float4 acc[2][4];
    #pragma unroll
    for (int mt = 0; mt < 2; mt++)
        #pragma unroll
        for (int nt = 0; nt < 4; nt++) acc[mt][nt] = make_float4(0.f, 0.f, 0.f, 0.f);

    #pragma unroll
    for (int ks = 0; ks < 8; ks++) {
        uint4 A0, A1, B0, B1;
        ldsm4(A0, aBase + ks * 32);
        ldsm4(A1, aBase + ks * 32 + 4352);   // +16 rows (16*272B)
        ldsm4t(B0, bBase + ks * 2304);       // +16 k-rows (16*144B)
        ldsm4t(B1, bBase + ks * 2304 + 32);  // +16 n-cols
        mma16(acc[0][0], A0.x, A0.y, A0.z, A0.w, B0.x, B0.y);
        mma16(acc[0][1], A0.x, A0.y, A0.z, A0.w, B0.z, B0.w);
        mma16(acc[0][2], A0.x, A0.y, A0.z, A0.w, B1.x, B1.y);
        mma16(acc[0][3], A0.x, A0.y, A0.z, A0.w, B1.z, B1.w);
        mma16(acc[1][0], A1.x, A1.y, A1.z, A1.w, B0.x, B0.y);
        mma16(acc[1][1], A1.x, A1.y, A1.z, A1.w, B0.z, B0.w);
        mma16(acc[1][2], A1.x, A1.y, A1.z, A1.w, B1.x, B1.y);
        mma16(acc[1][3], A1.x, A1.y, A1.z, A1.w, B1.z, B1.w);
    }

    #pragma unroll
    for (int mt = 0; mt < 2; mt++) {
        int p_lo = p0 + wm * 32 + mt * 16 + gid;
        int p_hi = p_lo + 8;
        #pragma unroll
        for (int nt = 0; nt < 4; nt++) {
            int c0 = n0 + wn * 32 + nt * 8 + 2 * tig;
            float2 bo2 = *(const float2*)(bo + c0);
            *(float2*)(out + (size_t)p_lo * CIN + c0) =
                make_float2(acc[mt][nt].x + bo2.x, acc[mt][nt].y + bo2.y);
            *(float2*)(out + (size_t)p_hi * CIN + c0) =
                make_float2(acc[mt][nt].z + bo2.x, acc[mt][nt].w + bo2.y);
        }
    }
}

extern "C" void kernel_launch(void* const* d_in, const int* in_sizes, int n_in,
                              void* d_out, int out_size) {
    (void)in_sizes; (void)n_in; (void)out_size;
    const float* x    = (const float*)d_in[0];
    const float* mask = (const float*)d_in[1];
    const float* lnw  = (const float*)d_in[2];
    const float* lnb  = (const float*)d_in[3];
    const float* wb   = (const float*)d_in[4];
    const float* wq   = (const float*)d_in[5];
    const float* wk   = (const float*)d_in[6];
    const float* wv   = (const float*)d_in[7];
    const float* wg   = (const float*)d_in[8];
    const float* bg   = (const float*)d_in[9];
    const float* wo   = (const float*)d_in[10];
    const float* bo   = (const float*)d_in[11];
    float* out = (float*)d_out;

    cudaFuncSetAttribute(lnproj_kernel,  cudaFuncAttributeMaxDynamicSharedMemorySize, (int)sizeof(LnSmem));
    cudaFuncSetAttribute(attn_kernel,    cudaFuncAttributeMaxDynamicSharedMemorySize, (int)sizeof(AttnSmem));
    cudaFuncSetAttribute(outproj_kernel, cudaFuncAttributeMaxDynamicSharedMemorySize, (int)sizeof(OutSmem));

    prep_kernel<<<256, 256>>>(wb, wq, wk, wv, wg, wo);
    lnproj_kernel<<<512, 256, sizeof(LnSmem)>>>(x, lnw, lnb, bg);
    attn_kernel<<<1024, 256, sizeof(AttnSmem)>>>(mask);
    outproj_kernel<<<1024, 256, sizeof(OutSmem)>>>(out, bo);
}

// round 14
// speedup vs baseline: 1.2300x; 1.0716x over previous
#include <cuda_runtime.h>
#include <cuda_fp16.h>
#include <math.h>

#define NN   256
#define CIN  128
#define HH   4
#define DD   32
#define NPOS (NN*NN)
#define FULL 0xffffffffu
#define LOG2E 1.4426950408889634f

// ---------------- scratch (device globals) ----------------
__device__ __half g_Wh[CIN][512];          // [c][e] fp16: e<128 wq*scale*log2e, <256 wk, <384 wv, <512 wg
__device__ float  g_wbt[HH][CIN];          // tri-bias weights f32 (x log2e)
__device__ __half g_Woh[CIN][CIN];         // [e][c] = w_o[c][e] fp16
__device__ __half g_q[NN][HH][NN][DD];
__device__ __half g_k[NN][HH][NN][DD];
__device__ __half g_v[NN][HH][NN][DD];
__device__ __half g_gate[(size_t)NPOS*CIN];
__device__ __half g_tbh[HH][NN][NN];       // [h][query][key] fp16, pre-scaled by log2e
__device__ __half g_o[(size_t)NPOS*CIN];

// ---------------- helpers ----------------
__device__ __forceinline__ unsigned cvta_s(const void* p) {
    return (unsigned)__cvta_generic_to_shared(p);
}
__device__ __forceinline__ void cpa16(unsigned dst, const void* src) {
    asm volatile("cp.async.cg.shared.global [%0], [%1], 16;" :: "r"(dst), "l"(src) : "memory");
}
#define CPA_COMMIT() asm volatile("cp.async.commit_group;" ::: "memory")
#define CPA_WAIT0()  asm volatile("cp.async.wait_group 0;" ::: "memory")

__device__ __forceinline__ void ldsm4(uint4& d, unsigned a) {
    asm volatile("ldmatrix.sync.aligned.m8n8.x4.shared.b16 {%0,%1,%2,%3}, [%4];"
                 : "=r"(d.x), "=r"(d.y), "=r"(d.z), "=r"(d.w) : "r"(a));
}
__device__ __forceinline__ void ldsm4t(uint4& d, unsigned a) {
    asm volatile("ldmatrix.sync.aligned.m8n8.x4.trans.shared.b16 {%0,%1,%2,%3}, [%4];"
                 : "=r"(d.x), "=r"(d.y), "=r"(d.z), "=r"(d.w) : "r"(a));
}
// NON-volatile: lets ptxas schedule loads/MUFU across mmas.
__device__ __forceinline__ void mma16(float4& d, unsigned a0, unsigned a1, unsigned a2, unsigned a3,
                                      unsigned b0, unsigned b1) {
    asm("mma.sync.aligned.m16n8k16.row.col.f32.f16.f16.f32 "
        "{%0,%1,%2,%3},{%4,%5,%6,%7},{%8,%9},{%0,%1,%2,%3};"
        : "+f"(d.x), "+f"(d.y), "+f"(d.z), "+f"(d.w)
        : "r"(a0), "r"(a1), "r"(a2), "r"(a3), "r"(b0), "r"(b1));
}
__device__ __forceinline__ unsigned packh2(float lo, float hi) {
    unsigned r;
    asm("cvt.rn.f16x2.f32 %0, %1, %2;" : "=r"(r) : "f"(hi), "f"(lo));
    return r;
}
// raw 2^x (log2e pre-folded into scores)
__device__ __forceinline__ float ex2f(float x) {
    float r;
    asm("ex2.approx.f32 %0, %1;" : "=f"(r) : "f"(x));
    return r;
}

// ---------------- weight prep ----------------
__global__ void prep_kernel(const float* __restrict__ wb, const float* __restrict__ wq,
                            const float* __restrict__ wk, const float* __restrict__ wv,
                            const float* __restrict__ wg, const float* __restrict__ wo) {
    int idx = blockIdx.x * blockDim.x + threadIdx.x;
    if (idx < CIN * 512) {
        int c = idx >> 9, e = idx & 511;
        float val;
        if      (e < 128) val = wq[e * CIN + c] * (0.17677669529663687f * LOG2E);
        else if (e < 256) val = wk[(e - 128) * CIN + c];
        else if (e < 384) val = wv[(e - 256) * CIN + c];
        else              val = wg[(e - 384) * CIN + c];
        g_Wh[c][e] = __float2half(val);
    }
    if (idx < HH * CIN) {
        int h = idx >> 7, c = idx & 127;
        g_wbt[h][c] = wb[h * CIN + c] * LOG2E;
    }
    if (idx < CIN * CIN) {
        int e = idx >> 7, c = idx & 127;
        g_Woh[e][c] = __float2half(wo[c * CIN + e]);
    }
}

// ---------------- fused LN + {q,k,v,gate} fp16-mma projection + tri-bias ----------------
struct LnSmem {
    __half xs[128][136];       // 128 data cols + 8 pad (row 272B)
    __half Bs[2][128][72];     // cp.async double-buffered 64-col weight chunks (row 144B)
    float mu[128], rs[128];
};

__global__ __launch_bounds__(256) void lnproj_kernel(const float* __restrict__ x,
                                                     const float* __restrict__ lnw,
                                                     const float* __restrict__ lnb,
                                                     const float* __restrict__ bg) {
    extern __shared__ char sraw[];
    LnSmem& S = *(LnSmem*)sraw;

    int t = threadIdx.x;
    int p0 = blockIdx.x * 128;
    int w = t >> 5, lane = t & 31;
    int gid = lane >> 2, tig = lane & 3;

    // kick off async load of weight chunk 0 (independent of LN work)
    for (int f = t; f < 1024; f += 256) {
        int k = f >> 3, c8 = (f & 7) * 8;
        cpa16(cvta_s(&S.Bs[0][k][c8]), &g_Wh[k][c8]);
    }
    CPA_COMMIT();

    // LN stats
    for (int rr = 0; rr < 16; rr++) {
        int r = w * 16 + rr;
        const float* xp = x + (size_t)(p0 + r) * CIN;
        float v0 = xp[lane], v1 = xp[lane + 32], v2 = xp[lane + 64], v3 = xp[lane + 96];
        float s = v0 + v1 + v2 + v3;
        float q = v0 * v0 + v1 * v1 + v2 * v2 + v3 * v3;
        #pragma unroll
        for (int off = 16; off; off >>= 1) {
            s += __shfl_down_sync(FULL, s, off);
            q += __shfl_down_sync(FULL, q, off);
        }
        if (lane == 0) {
            float m = s * (1.f / 128.f);
            S.mu[r] = m;
            S.rs[r] = rsqrtf(q * (1.f / 128.f) - m * m + 1e-5f);
        }
    }
    __syncthreads();

    // normalize -> fp16 xs
    for (int idx = t * 4; idx < 128 * 128; idx += 1024) {
        int r = idx >> 7, c = idx & 127;
        float4 xv = *(const float4*)(x + (size_t)(p0 + r) * CIN + c);
        float4 wv = *(const float4*)(lnw + c);
        float4 bv = *(const float4*)(lnb + c);
        float m = S.mu[r], rs = S.rs[r];
        *(__half2*)&S.xs[r][c]     = __floats2half2_rn((xv.x - m) * rs * wv.x + bv.x,
                                                       (xv.y - m) * rs * wv.y + bv.y);
        *(__half2*)&S.xs[r][c + 2] = __floats2half2_rn((xv.z - m) * rs * wv.z + bv.z,
                                                       (xv.w - m) * rs * wv.w + bv.w);
    }
    CPA_WAIT0();
    __syncthreads();

    int wm = w >> 1, wn = w & 1;              // warp tile: 32 rows x 32 cols of 64-chunk
    int m8 = lane >> 3, r8 = lane & 7;

    unsigned aBase = cvta_s(&S.xs[wm * 32 + (m8 & 1) * 8 + r8][(m8 >> 1) * 8]);
    unsigned bBase[2];
    bBase[0] = cvta_s(&S.Bs[0][(m8 & 1) * 8 + r8][wn * 32 + (m8 >> 1) * 8]);
    bBase[1] = cvta_s(&S.Bs[1][(m8 & 1) * 8 + r8][wn * 32 + (m8 >> 1) * 8]);

    int p_lo0 = p0 + wm * 32 + gid;
    int ii = p_lo0 >> 8;

    for (int nc = 0; nc < 8; nc++) {
        int cur = nc & 1;
        // async prefetch of next chunk overlaps with this chunk's mmas
        if (nc < 7) {
            for (int f = t; f < 1024; f += 256) {
                int k = f >> 3, c8 = (f & 7) * 8;
                cpa16(cvta_s(&S.Bs[cur ^ 1][k][c8]), &g_Wh[k][(nc + 1) * 64 + c8]);
            }
            CPA_COMMIT();
        }

        float4 acc[2][4];
        #pragma unroll
        for (int mt = 0; mt < 2; mt++)
            #pragma unroll
            for (int nt = 0; nt < 4; nt++) acc[mt][nt] = make_float4(0.f, 0.f, 0.f, 0.f);

        unsigned bb = bBase[cur];
        #pragma unroll
        for (int ks = 0; ks < 8; ks++) {
            uint4 A0, A1, B0, B1;
            ldsm4(A0, aBase + ks * 32);
            ldsm4(A1, aBase + ks * 32 + 4352);     // +16 rows (16*272B)
            ldsm4t(B0, bb + ks * 2304);            // +16 k-rows (16*144B)
            ldsm4t(B1, bb + ks * 2304 + 32);       // +16 n-cols
            mma16(acc[0][0], A0.x, A0.y, A0.z, A0.w, B0.x, B0.y);
            mma16(acc[0][1], A0.x, A0.y, A0.z, A0.w, B0.z, B0.w);
            mma16(acc[0][2], A0.x, A0.y, A0.z, A0.w, B1.x, B1.y);
            mma16(acc[0][3], A0.x, A0.y, A0.z, A0.w, B1.z, B1.w);
            mma16(acc[1][0], A1.x, A1.y, A1.z, A1.w, B0.x, B0.y);
            mma16(acc[1][1], A1.x, A1.y, A1.z, A1.w, B0.z, B0.w);
            mma16(acc[1][2], A1.x, A1.y, A1.z, A1.w, B1.x, B1.y);
            mma16(acc[1][3], A1.x, A1.y, A1.z, A1.w, B1.z, B1.w);
        }

        // epilogue to gmem
        int sel = nc >> 1;   // 0=q 1=k 2=v 3=gate
        #pragma unroll
        for (int mt = 0; mt < 2; mt++) {
            int p_lo = p_lo0 + mt * 16;
            int jj_lo = p_lo & 255, jj_hi = jj_lo + 8;
            #pragma unroll
            for (int nt = 0; nt < 4; nt++) {
                int e0 = nc * 64 + wn * 32 + nt * 8 + 2 * tig;
                int loc = e0 & 127;
                int hh = loc >> 5, d0 = loc & 31;
                float4 a = acc[mt][nt];
                if (sel == 0) {
                    *(__half2*)&g_q[ii][hh][jj_lo][d0] = __floats2half2_rn(a.x, a.y);
                    *(__half2*)&g_q[ii][hh][jj_hi][d0] = __floats2half2_rn(a.z, a.w);
                } else if (sel == 1) {
                    *(__half2*)&g_k[ii][hh][jj_lo][d0] = __floats2half2_rn(a.x, a.y);
                    *(__half2*)&g_k[ii][hh][jj_hi][d0] = __floats2half2_rn(a.z, a.w);
                } else if (sel == 2) {
                    *(__half2*)&g_v[ii][hh][jj_lo][d0] = __floats2half2_rn(a.x, a.y);
                    *(__half2*)&g_v[ii][hh][jj_hi][d0] = __floats2half2_rn(a.z, a.w);
                } else {
                    float2 bg2 = *(const float2*)(bg + loc);
                    float glx = 1.f / (1.f + __expf(-(a.x + bg2.x)));
                    float gly = 1.f / (1.f + __expf(-(a.y + bg2.y)));
                    float ghx = 1.f / (1.f + __expf(-(a.z + bg2.x)));
                    float ghy = 1.f / (1.f + __expf(-(a.w + bg2.y)));
                    *(__half2*)(g_gate + (size_t)p_lo * CIN + loc) = __floats2half2_rn(glx, gly);
                    *(__half2*)(g_gate + ((size_t)p_lo + 8) * CIN + loc) = __floats2half2_rn(ghx, ghy);
                }
            }
        }

        if (nc < 7) CPA_WAIT0();
        __syncthreads();
    }

    // triangle bias (fp16 out, pre-scaled by log2e via g_wbt)
    for (int pp = t; pp < 512; pp += 256) {
        int rr = pp >> 2, hh = pp & 3;
        const float* wv = g_wbt[hh];
        float a = 0.f;
        #pragma unroll 16
        for (int c = 0; c < 128; c += 2) {
            float2 fx = __half22float2(*(__half2*)&S.xs[rr][c]);
            a += fx.x * wv[c] + fx.y * wv[c + 1];
        }
        int p = p0 + rr;
        g_tbh[hh][p >> 8][p & 255] = __float2half(a);
    }
}

// ---------------- fp16-mma flash attention + gating ----------------
// CTA = (i, h): 256 threads, 8 warps, warp owns 32 queries. K/V staged once;
// tri-bias tile double-buffered via cp.async (row stride 80B = 16B-aligned);
// softmax denominator via ones-column mma.
struct AttnSmem {
    __half Qs[256][40];       // 20 KB
    __half Ks[256][40];       // 20 KB
    __half Vs[256][40];       // 20 KB
    __half Tb[2][256][40];    // 40 KB: tb tile [q][32k] + 8 pad (row 80B, cp.async-aligned)
    float mbs[256];           // 1 KB
};

__global__ __launch_bounds__(256, 2) void attn_kernel(const float* __restrict__ mask) {
    extern __shared__ char sraw[];
    AttnSmem& S = *(AttnSmem*)sraw;

    int bid = blockIdx.x;
    int i = bid >> 2;
    int h = bid & 3;
    int t = threadIdx.x;
    int w = t >> 5, lane = t & 31;
    int gid = lane >> 2, tig = lane & 3;

    const __half* qg = &g_q[i][h][0][0];
    const __half* kg = &g_k[i][h][0][0];
    const __half* vg = &g_v[i][h][0][0];
    const __half* tb_g = &g_tbh[h][0][0];

    for (int f = t; f < 1024; f += 256) {
        int r = f >> 2, c8 = (f & 3) * 8;
        cpa16(cvta_s(&S.Qs[r][c8]), qg + r * 32 + c8);
        cpa16(cvta_s(&S.Ks[r][c8]), kg + r * 32 + c8);
        cpa16(cvta_s(&S.Vs[r][c8]), vg + r * 32 + c8);
    }
    // tb tile for kb=0
    for (int f = t; f < 1024; f += 256) {
        int q = f >> 2, c = (f & 3) * 8;
        cpa16(cvta_s(&S.Tb[0][q][c]), tb_g + q * NN + c);
    }
    CPA_COMMIT();
    S.mbs[t] = (1e9f * LOG2E) * (mask[i * NN + t] - 1.0f);
    CPA_WAIT0();
    __syncthreads();

    int m8 = lane >> 3, r8 = lane & 7;

    // Q fragments: warp rows w*32..w*32+31, 2 m-tiles x 2 ksteps
    unsigned qA = cvta_s(&S.Qs[w * 32 + (m8 & 1) * 8 + r8][(m8 >> 1) * 8]);
    uint4 aq[2][2];
    #pragma unroll
    for (int mt = 0; mt < 2; mt++) {
        ldsm4(aq[mt][0], qA + mt * 1280);        // +16 rows (16*80B)
        ldsm4(aq[mt][1], qA + mt * 1280 + 32);   // +16 cols (d16-31)
    }

    unsigned kA = cvta_s(&S.Ks[(m8 & 1) * 8 + r8][(m8 >> 1) * 8]);
    unsigned vA = cvta_s(&S.Vs[(m8 & 1) * 8 + r8][(m8 >> 1) * 8]);

    float4 oacc[2][4];
    float4 lacc[2];
    #pragma unroll
    for (int mt = 0; mt < 2; mt++) {
        #pragma unroll
        for (int n = 0; n < 4; n++) oacc[mt][n] = make_float4(0.f, 0.f, 0.f, 0.f);
        lacc[mt] = make_float4(0.f, 0.f, 0.f, 0.f);
    }
    // ones-column B fragment: B[k][0]=1 else 0 -> lanes with gid==0 hold {1,1}
    unsigned bone = (gid == 0) ? 0x3C003C00u : 0u;

    int q_row0 = w * 32 + gid;     // mt adds +16, hi adds +8
    int cur = 0;

    for (int kb = 0; kb < 8; kb++) {
        int kbase = kb * 32;

        // prefetch next tb tile (overlaps with this block's compute)
        if (kb < 7) {
            int nb = kbase + 32;
            for (int f = t; f < 1024; f += 256) {
                int q = f >> 2, c = (f & 3) * 8;
                cpa16(cvta_s(&S.Tb[cur ^ 1][q][c]), tb_g + q * NN + nb + c);
            }
            CPA_COMMIT();
        }

        // S = Q @ K^T for 32 keys (K [key][d] col-major kxn -> NON-trans ldsm)
        float4 s[2][4];
        #pragma unroll
        for (int mt = 0; mt < 2; mt++)
            #pragma unroll
            for (int nt = 0; nt < 4; nt++) s[mt][nt] = make_float4(0.f, 0.f, 0.f, 0.f);

        #pragma unroll
        for (int ntp = 0; ntp < 2; ntp++) {
            unsigned ka = kA + (kbase + ntp * 16) * 80;
            uint4 B0, B1;
            ldsm4(B0, ka);
            ldsm4(B1, ka + 32);
            #pragma unroll
            for (int mt = 0; mt < 2; mt++) {
                mma16(s[mt][2 * ntp],     aq[mt][0].x, aq[mt][0].y, aq[mt][0].z, aq[mt][0].w, B0.x, B0.z);
                mma16(s[mt][2 * ntp],     aq[mt][1].x, aq[mt][1].y, aq[mt][1].z, aq[mt][1].w, B1.x, B1.z);
                mma16(s[mt][2 * ntp + 1], aq[mt][0].x, aq[mt][0].y, aq[mt][0].z, aq[mt][0].w, B0.y, B0.w);
                mma16(s[mt][2 * ntp + 1], aq[mt][1].x, aq[mt][1].y, aq[mt][1].z, aq[mt][1].w, B1.y, B1.w);
            }
        }

        // V fragments hoisted: independent of S, LDSM latency hides under exp below
        uint4 Vf[2][2];
        #pragma unroll
        for (int ktp = 0; ktp < 2; ktp++) {
            unsigned va = vA + (kbase + ktp * 16) * 80;
            ldsm4t(Vf[ktp][0], va);
            ldsm4t(Vf[ktp][1], va + 32);
        }

        // bias (tb from smem) + 2^x + pack to fp16 A-fragments
        unsigned pa[2][2][4];
        #pragma unroll
        for (int mt = 0; mt < 2; mt++) {
            int qlo = q_row0 + mt * 16;
            #pragma unroll
            for (int nt = 0; nt < 4; nt++) {
                int lk = nt * 8 + 2 * tig;
                float2 tl = __half22float2(*(__half2*)&S.Tb[cur][qlo][lk]);
                float2 th = __half22float2(*(__half2*)&S.Tb[cur][qlo + 8][lk]);
                int c0 = kbase + lk;
                float mb0 = S.mbs[c0], mb1 = S.mbs[c0 + 1];
                float px = ex2f(s[mt][nt].x + tl.x + mb0);
                float py = ex2f(s[mt][nt].y + tl.y + mb1);
                float pz = ex2f(s[mt][nt].z + th.x + mb0);
                float pw = ex2f(s[mt][nt].w + th.y + mb1);
                int ktp = nt >> 1;
                if (!(nt & 1)) {
                    pa[mt][ktp][0] = packh2(px, py);
                    pa[mt][ktp][1] = packh2(pz, pw);
                } else {
                    pa[mt][ktp][2] = packh2(px, py);
                    pa[mt][ktp][3] = packh2(pz, pw);
                }
            }
        }

        // O += P @ V, and l += P @ ones (extra column)
        #pragma unroll
        for (int ktp = 0; ktp < 2; ktp++) {
            #pragma unroll
            for (int mt = 0; mt < 2; mt++) {
                mma16(oacc[mt][0], pa[mt][ktp][0], pa[mt][ktp][1], pa[mt][ktp][2], pa[mt][ktp][3], Vf[ktp][0].x, Vf[ktp][0].y);
                mma16(oacc[mt][1], pa[mt][ktp][0], pa[mt][ktp][1], pa[mt][ktp][2], pa[mt][ktp][3], Vf[ktp][0].z, Vf[ktp][0].w);
                mma16(oacc[mt][2], pa[mt][ktp][0], pa[mt][ktp][1], pa[mt][ktp][2], pa[mt][ktp][3], Vf[ktp][1].x, Vf[ktp][1].y);
                mma16(oacc[mt][3], pa[mt][ktp][0], pa[mt][ktp][1], pa[mt][ktp][2], pa[mt][ktp][3], Vf[ktp][1].z, Vf[ktp][1].w);
                mma16(lacc[mt],    pa[mt][ktp][0], pa[mt][ktp][1], pa[mt][ktp][2], pa[mt][ktp][3], bone, bone);
            }
        }

        if (kb < 7) {
            CPA_WAIT0();
            __syncthreads();
        }
        cur ^= 1;
    }

    // finalize + gated store (l broadcast from tig==0 lanes)
    #pragma unroll
    for (int mt = 0; mt < 2; mt++) {
        float ll = __shfl_sync(FULL, lacc[mt].x, lane & ~3);
        float lh = __shfl_sync(FULL, lacc[mt].z, lane & ~3);
        float inv_lo = 1.f / ll, inv_hi = 1.f / lh;

        int q_lo = q_row0 + mt * 16, q_hi = q_lo + 8;
        size_t base_lo = ((size_t)(i * NN + q_lo)) * CIN + h * DD;
        size_t base_hi = ((size_t)(i * NN + q_hi)) * CIN + h * DD;
        #pragma unroll
        for (int ntd = 0; ntd < 4; ntd++) {
            int d0 = ntd * 8 + 2 * tig;
            float2 gl = __half22float2(*(__half2*)(g_gate + base_lo + d0));
            float2 gh = __half22float2(*(__half2*)(g_gate + base_hi + d0));
            *(__half2*)(g_o + base_lo + d0) =
                __floats2half2_rn(oacc[mt][ntd].x * inv_lo * gl.x, oacc[mt][ntd].y * inv_lo * gl.y);
            *(__half2*)(g_o + base_hi + d0) =
                __floats2half2_rn(oacc[mt][ntd].z * inv_hi * gh.x, oacc[mt][ntd].w * inv_hi * gh.y);
        }
    }
}

// ---------------- fp16-mma output projection: split-N (128 rows x 64 cols per CTA) ----------------
struct OutSmem {
    __half os[128][136];    // full 128-col activations
    __half Ws[128][72];     // this CTA's 64 weight cols
};

__global__ __launch_bounds__(256, 3) void outproj_kernel(float* __restrict__ out,
                                                         const float* __restrict__ bo) {
    extern __shared__ char sraw[];
    OutSmem& S = *(OutSmem*)sraw;

    int bid = blockIdx.x;
    int p0 = (bid >> 1) * 128;
    int n0 = (bid & 1) * 64;
    int t = threadIdx.x;
    int w = t >> 5, lane = t & 31;
    int gid = lane >> 2, tig = lane & 3;

    for (int f = t; f < 2048; f += 256) {
        int r = f >> 4, c8 = (f & 15) * 8;
        cpa16(cvta_s(&S.os[r][c8]), g_o + (size_t)(p0 + r) * CIN + c8);
    }
    for (int f = t; f < 1024; f += 256) {
        int r = f >> 3, c8 = (f & 7) * 8;
        cpa16(cvta_s(&S.Ws[r][c8]), &g_Woh[r][n0 + c8]);
    }
    CPA_COMMIT();
    CPA_WAIT0();
    __syncthreads();

    int wm = w >> 1, wn = w & 1;           // warp tile 32 rows x 32 cols
    int m8 = lane >> 3, r8 = lane & 7;

    unsigned aBase = cvta_s(&S.os[wm * 32 + (m8 & 1) * 8 + r8][(m8 >> 1) * 8]);
    unsigned bBase = cvta_s(&S.Ws[(m8 & 1) * 8 + r8][wn * 32 + (m8 >> 1) * 8]);

    float4 acc[2][4];
    #pragma unroll
    for (int mt = 0; mt < 2; mt++)
        #pragma unroll
        for (int nt = 0; nt < 4; nt++) acc[mt][nt] = make_float4(0.f, 0.f, 0.f, 0.f);

    #pragma unroll
    for (int ks = 0; ks < 8; ks++) {
        uint4 A0, A1, B0, B1;
        ldsm4(A0, aBase + ks * 32);
        ldsm4(A1, aBase + ks * 32 + 4352);   // +16 rows (16*272B)
        ldsm4t(B0, bBase + ks * 2304);       // +16 k-rows (16*144B)
        ldsm4t(B1, bBase + ks * 2304 + 32);  // +16 n-cols
        mma16(acc[0][0], A0.x, A0.y, A0.z, A0.w, B0.x, B0.y);
        mma16(acc[0][1], A0.x, A0.y, A0.z, A0.w, B0.z, B0.w);
        mma16(acc[0][2], A0.x, A0.y, A0.z, A0.w, B1.x, B1.y);
        mma16(acc[0][3], A0.x, A0.y, A0.z, A0.w, B1.z, B1.w);
        mma16(acc[1][0], A1.x, A1.y, A1.z, A1.w, B0.x, B0.y);
        mma16(acc[1][1], A1.x, A1.y, A1.z, A1.w, B0.z, B0.w);
        mma16(acc[1][2], A1.x, A1.y, A1.z, A1.w, B1.x, B1.y);
        mma16(acc[1][3], A1.x, A1.y, A1.z, A1.w, B1.z, B1.w);
    }

    #pragma unroll
    for (int mt = 0; mt < 2; mt++) {
        int p_lo = p0 + wm * 32 + mt * 16 + gid;
        int p_hi = p_lo + 8;
        #pragma unroll
        for (int nt = 0; nt < 4; nt++) {
            int c0 = n0 + wn * 32 + nt * 8 + 2 * tig;
            float2 bo2 = *(const float2*)(bo + c0);
            *(float2*)(out + (size_t)p_lo * CIN + c0) =
                make_float2(acc[mt][nt].x + bo2.x, acc[mt][nt].y + bo2.y);
            *(float2*)(out + (size_t)p_hi * CIN + c0) =
                make_float2(acc[mt][nt].z + bo2.x, acc[mt][nt].w + bo2.y);
        }
    }
}

extern "C" void kernel_launch(void* const* d_in, const int* in_sizes, int n_in,
                              void* d_out, int out_size) {
    (void)in_sizes; (void)n_in; (void)out_size;
    const float* x    = (const float*)d_in[0];
    const float* mask = (const float*)d_in[1];
    const float* lnw  = (const float*)d_in[2];
    const float* lnb  = (const float*)d_in[3];
    const float* wb   = (const float*)d_in[4];
    const float* wq   = (const float*)d_in[5];
    const float* wk   = (const float*)d_in[6];
    const float* wv   = (const float*)d_in[7];
    const float* wg   = (const float*)d_in[8];
    const float* bg   = (const float*)d_in[9];
    const float* wo   = (const float*)d_in[10];
    const float* bo   = (const float*)d_in[11];
    float* out = (float*)d_out;

    cudaFuncSetAttribute(lnproj_kernel,  cudaFuncAttributeMaxDynamicSharedMemorySize, (int)sizeof(LnSmem));
    cudaFuncSetAttribute(attn_kernel,    cudaFuncAttributeMaxDynamicSharedMemorySize, (int)sizeof(AttnSmem));
    cudaFuncSetAttribute(outproj_kernel, cudaFuncAttributeMaxDynamicSharedMemorySize, (int)sizeof(OutSmem));

    prep_kernel<<<256, 256>>>(wb, wq, wk, wv, wg, wo);
    lnproj_kernel<<<512, 256, sizeof(LnSmem)>>>(x, lnw, lnb, bg);
    attn_kernel<<<1024, 256, sizeof(AttnSmem)>>>(mask);
    outproj_kernel<<<1024, 256, sizeof(OutSmem)>>>(out, bo);
}